// round 3
// baseline (speedup 1.0000x reference)
#include <cuda_runtime.h>

// ---------------------------------------------------------------------------
// MultiheadLocalAttentionV1: N=2, C=256, H=8, HD=32, 32x32 spatial,
// 15x15 window (225 taps), dilation 1, pad 7.
//
// Pipeline:
//   K1 proj_kernel   : qp/kp/vp = 1x1 conv (GEMM 2048x256x256), q scaled 1/T,
//                      stored in (n,h,p,hd) layout for the attention kernel.
//   K2 rvT_kernel    : transpose rel_v (H,HD,WS2) -> (H,WS2,HD) once.
//   K3 attn_kernel   : per (n,h,8x2 pixel tile): load 16x22 zero-padded K halo
//                      to smem, fuse rel logits (qs . T*Wrk_s + brk_s) into the
//                      qk dot, softmax (warp/pixel), write attn probs, then
//                      reload halo with V (+rel_v) and accumulate the output.
//   K4 final_kernel  : out = ao @ Wp^T + bp  (GEMM 2048x256x256), laid out
//                      (hw, n, C) as the reference's final reshape demands.
// ---------------------------------------------------------------------------

#define NB      2
#define HNUM    8
#define HDim    32
#define CCH     256
#define WDIM    32
#define HW      1024
#define WS      15
#define WS2     225
#define MAXDIS  7

#define TW      8          // tile width  (pixels)
#define TH      2          // tile height (pixels)
#define TPIX    16         // pixels per attention block
#define HR      (TH + 14)  // halo rows = 16
#define HC      (TW + 14)  // halo cols = 22
#define NHALO   (HR * HC)  // 352
#define KSTR    36         // smem row stride (floats): 16B aligned, conflict-free
#define ASTR    240        // attn smem row stride

#define T_CONST 5.656854249492381f    // sqrt(32)
#define INV_T   0.17677669529663689f  // 1/sqrt(32)

#define OUT_ELEMS  (HW * NB * CCH)               // 524288
#define ATTN_ELEMS (NB * HNUM * WS2 * HW)        // 3686400

// smem layout of attention kernel (floats)
#define S_K 0
#define S_W (NHALO * KSTR)                 // 12672
#define S_A (S_W + WS2 * KSTR)             // 12672 + 8100 = 20772
#define S_Q (S_A + TPIX * ASTR)            // + 3840 = 24612
#define SMEM_FLOATS (S_Q + TPIX * HDim)    // + 512 = 25124
#define SMEM_BYTES  (SMEM_FLOATS * 4)      // 100496 B

// -------------------------- scratch (no cudaMalloc allowed) ----------------
__device__ float g_qs[NB * HNUM * HW * HDim];   // scaled q   (n,h,p,hd)
__device__ float g_kp[NB * HNUM * HW * HDim];   // projected k
__device__ float g_vp[NB * HNUM * HW * HDim];   // projected v
__device__ float g_ao[NB * HW * CCH];           // attention output (n,p,ch)
__device__ float g_rvT[HNUM * WS2 * HDim];      // rel_v transposed (h,s,hd)

// ---------------------------------------------------------------------------
// K1: fused QKV projection. blockIdx.y selects matrix (0=Q,1=K,2=V).
// Each block: 32 pixels x 256 output channels, 256 threads (1 thread / out ch).
// ---------------------------------------------------------------------------
__global__ __launch_bounds__(256) void proj_kernel(
    const float* __restrict__ q, const float* __restrict__ k, const float* __restrict__ v,
    const float* __restrict__ WQ, const float* __restrict__ WK, const float* __restrict__ WV,
    const float* __restrict__ bQ, const float* __restrict__ bK, const float* __restrict__ bV)
{
    __shared__ float xs[32 * 256];   // xs[c][px] : xs[c*32 + px]

    const int m = blockIdx.y;
    const float* x = (m == 0) ? q : (m == 1) ? k : v;
    const float* W = (m == 0) ? WQ : (m == 1) ? WK : WV;
    const float* b = (m == 0) ? bQ : (m == 1) ? bK : bV;
    float* out     = (m == 0) ? g_qs : (m == 1) ? g_kp : g_vp;
    const float scale = (m == 0) ? INV_T : 1.0f;

    const int gp0 = blockIdx.x * 32;       // global pixel base (0..2047)
    const int n   = gp0 >> 10;
    const int p0  = gp0 & 1023;
    const int t   = threadIdx.x;
    const int lane = t & 31;
    const int cg   = t >> 5;

    // cooperative load: coalesced over pixels, xs[c][px]
    for (int c = cg; c < 256; c += 8)
        xs[c * 32 + lane] = x[(n * 256 + c) * HW + p0 + lane];
    __syncthreads();

    float acc[32];
#pragma unroll
    for (int i = 0; i < 32; i++) acc[i] = 0.f;

    const float* Wr = W + t * 256;
    for (int c = 0; c < 256; c += 4) {
        float4 w4 = *(const float4*)(Wr + c);
        float wv[4] = {w4.x, w4.y, w4.z, w4.w};
#pragma unroll
        for (int j = 0; j < 4; j++) {
#pragma unroll
            for (int p4 = 0; p4 < 8; p4++) {
                float4 xv = *(const float4*)&xs[(c + j) * 32 + p4 * 4];
                acc[p4 * 4 + 0] += wv[j] * xv.x;
                acc[p4 * 4 + 1] += wv[j] * xv.y;
                acc[p4 * 4 + 2] += wv[j] * xv.z;
                acc[p4 * 4 + 3] += wv[j] * xv.w;
            }
        }
    }

    const float bias = b[t];
    const int h  = t >> 5;
    const int hd = t & 31;
    float* op = out + ((size_t)(n * HNUM + h) * HW) * HDim + hd;
#pragma unroll
    for (int px = 0; px < 32; px++)
        op[(size_t)(p0 + px) * HDim] = (acc[px] + bias) * scale;
}

// ---------------------------------------------------------------------------
// K2: transpose rel_v (H,HD,WS2) -> (H,WS2,HD)
// ---------------------------------------------------------------------------
__global__ void rvT_kernel(const float* __restrict__ rel_v)
{
    int i = blockIdx.x * 256 + threadIdx.x;   // exactly 8*225*32 threads
    if (i < HNUM * WS2 * HDim) {
        int c = i & 31;
        int s = (i >> 5) % WS2;
        int h = i / (WS2 * HDim);
        g_rvT[i] = rel_v[(h * HDim + c) * WS2 + s];
    }
}

// ---------------------------------------------------------------------------
// K3: local attention. grid = (64 tiles, 8 heads, 2 batch), 256 threads.
// ---------------------------------------------------------------------------
extern __shared__ float sm[];

__global__ __launch_bounds__(256) void attn_kernel(
    const float* __restrict__ Wrk, const float* __restrict__ brk,
    float* __restrict__ attn_out)
{
    const int h = blockIdx.y;
    const int n = blockIdx.z;
    const int tileIdx = blockIdx.x;
    const int tx0 = (tileIdx & 3) * TW;   // 4 tiles across
    const int ty0 = (tileIdx >> 2) * TH;  // 16 tiles down
    const int t = threadIdx.x;
    const int nh = n * HNUM + h;

    const float* qs = g_qs + (size_t)nh * HW * HDim;
    const float* kp = g_kp + (size_t)nh * HW * HDim;
    const float* vp = g_vp + (size_t)nh * HW * HDim;

    float* ksm  = sm + S_K;   // K halo, later V halo     [NHALO][KSTR]
    float* wsm  = sm + S_W;   // T*Wrk, later rel_v^T     [WS2][KSTR]
    float* atsm = sm + S_A;   // logits -> probs          [TPIX][ASTR]
    float* qsm  = sm + S_Q;   // scaled q tile            [TPIX][32]

    // ---- load q tile ----
    for (int idx = t; idx < TPIX * 32; idx += 256) {
        int px = idx >> 5, c = idx & 31;
        int gy = ty0 + (px >> 3), gx = tx0 + (px & 7);
        qsm[idx] = qs[(gy * WDIM + gx) * HDim + c];
    }
    // ---- load K halo (zero padded) ----
    for (int idx = t; idx < NHALO * 32; idx += 256) {
        int hp = idx >> 5, c = idx & 31;
        int hy = hp / HC, hx = hp - hy * HC;
        int gy = ty0 - MAXDIS + hy, gx = tx0 - MAXDIS + hx;
        float vv = 0.f;
        if ((unsigned)gy < 32u && (unsigned)gx < 32u)
            vv = kp[(gy * WDIM + gx) * HDim + c];
        ksm[hp * KSTR + c] = vv;
    }
    // ---- load T * Wrk[h] ----
    for (int idx = t; idx < WS2 * 32; idx += 256) {
        int s = idx >> 5, c = idx & 31;
        wsm[s * KSTR + c] = T_CONST * Wrk[(h * WS2 + s) * HDim + c];
    }
    __syncthreads();

    // ---- logits: thread = window tap s ----
    if (t < WS2) {
        const int s  = t;
        const int kh = s / WS;
        const int kw = s - kh * WS;
        float wreg[32];
#pragma unroll
        for (int c = 0; c < 32; c++) wreg[c] = wsm[s * KSTR + c];
        const float bb = brk[h * WS2 + s];

#pragma unroll
        for (int py = 0; py < TH; py++) {
            const int gy = ty0 + py + kh - MAXDIS;
            const bool vy = ((unsigned)gy < 32u);
            const int hrow = (py + kh) * HC;
#pragma unroll
            for (int pxx = 0; pxx < TW; pxx++) {
                const int gx = tx0 + pxx + kw - MAXDIS;
                const float* kr = &ksm[(hrow + pxx + kw) * KSTR];
                const float* qr = &qsm[(py * TW + pxx) * 32];
                float a = bb;
#pragma unroll
                for (int c4 = 0; c4 < 32; c4 += 4) {
                    float4 qv = *(const float4*)(qr + c4);
                    float4 kv = *(const float4*)(kr + c4);
                    a += qv.x * kv.x + qv.y * kv.y + qv.z * kv.z + qv.w * kv.w;
                    a += qv.x * wreg[c4]     + qv.y * wreg[c4 + 1]
                       + qv.z * wreg[c4 + 2] + qv.w * wreg[c4 + 3];
                }
                if (!(vy && (unsigned)gx < 32u)) a -= 1e8f;
                atsm[(py * TW + pxx) * ASTR + s] = a;
            }
        }
    }
    __syncthreads();

    // ---- overwrite halo with V, wsm with rel_v^T (overlaps softmax latency) ----
    for (int idx = t; idx < NHALO * 32; idx += 256) {
        int hp = idx >> 5, c = idx & 31;
        int hy = hp / HC, hx = hp - hy * HC;
        int gy = ty0 - MAXDIS + hy, gx = tx0 - MAXDIS + hx;
        float vv = 0.f;
        if ((unsigned)gy < 32u && (unsigned)gx < 32u)
            vv = vp[(gy * WDIM + gx) * HDim + c];
        ksm[hp * KSTR + c] = vv;
    }
    for (int idx = t; idx < WS2 * 32; idx += 256) {
        int s = idx >> 5, c = idx & 31;
        wsm[s * KSTR + c] = g_rvT[(h * WS2 + s) * HDim + c];
    }

    // ---- softmax: warp per 2 pixels ----
    {
        const int warp = t >> 5, lane = t & 31;
#pragma unroll
        for (int pp = 0; pp < 2; pp++) {
            const int px = warp * 2 + pp;
            float* arow = &atsm[px * ASTR];
            float vals[8];
            float mx = -3.4e38f;
#pragma unroll
            for (int i = 0; i < 8; i++) {
                int s = lane + 32 * i;
                vals[i] = (s < WS2) ? arow[s] : -3.4e38f;
                mx = fmaxf(mx, vals[i]);
            }
#pragma unroll
            for (int off = 16; off; off >>= 1)
                mx = fmaxf(mx, __shfl_xor_sync(0xffffffffu, mx, off));
            float sum = 0.f;
#pragma unroll
            for (int i = 0; i < 8; i++) {
                int s = lane + 32 * i;
                float e = (s < WS2) ? __expf(vals[i] - mx) : 0.f;
                vals[i] = e;
                sum += e;
            }
#pragma unroll
            for (int off = 16; off; off >>= 1)
                sum += __shfl_xor_sync(0xffffffffu, sum, off);
            const float inv = 1.0f / sum;
#pragma unroll
            for (int i = 0; i < 8; i++) {
                int s = lane + 32 * i;
                if (s < WS2) arow[s] = vals[i] * inv;
            }
        }
    }
    __syncthreads();

    // ---- write attn probabilities (n,H,WS2,hw) ----
    if (attn_out) {
        float* ao = attn_out + (size_t)nh * WS2 * HW;
        for (int idx = t; idx < WS2 * TPIX; idx += 256) {
            int s = idx >> 4, px = idx & 15;
            int pgl = (ty0 + (px >> 3)) * WDIM + tx0 + (px & 7);
            ao[s * HW + pgl] = atsm[px * ASTR + s];
        }
    }

    // ---- output: out[px][c] = sum_s attn * (V + rel_v), thread = (pxb, c) ----
    {
        const int c   = t & 31;
        const int pxb = t >> 5;  // 0..7
#pragma unroll
        for (int rep = 0; rep < 2; rep++) {
            const int px  = pxb + rep * 8;
            const int py  = px >> 3;
            const int pxx = px & 7;
            const float* arow = &atsm[px * ASTR];
            float acc = 0.f, accr = 0.f;
#pragma unroll 3
            for (int kh = 0; kh < WS; kh++) {
                const int hbase = (py + kh) * HC + pxx;
                const int sbase = kh * WS;
#pragma unroll
                for (int kw = 0; kw < WS; kw++) {
                    const float a = arow[sbase + kw];
                    acc  += a * ksm[(hbase + kw) * KSTR + c];   // V
                    accr += a * wsm[(sbase + kw) * KSTR + c];   // rel_v
                }
            }
            const int gy = ty0 + py, gx = tx0 + pxx;
            g_ao[((size_t)n * HW + gy * WDIM + gx) * CCH + h * HDim + c] = acc + accr;
        }
    }
}

// ---------------------------------------------------------------------------
// K4: final projection: out[p,n,o] = sum_c ao[n,p,c]*Wp[o,c] + bp[o]
// ---------------------------------------------------------------------------
__global__ __launch_bounds__(256) void final_kernel(
    const float* __restrict__ Wp, const float* __restrict__ bp,
    float* __restrict__ out)
{
    __shared__ float xs[32 * 256];   // xs[px][c]

    const int gp0 = blockIdx.x * 32;
    const int n   = gp0 >> 10;
    const int p0  = gp0 & 1023;
    const int t   = threadIdx.x;

    const float* src = g_ao + ((size_t)n * HW + p0) * CCH;
    for (int idx = t; idx < 32 * 256; idx += 256)
        xs[idx] = src[idx];
    __syncthreads();

    float acc[32];
#pragma unroll
    for (int i = 0; i < 32; i++) acc[i] = 0.f;

    const float* Wr = Wp + t * 256;
    for (int c = 0; c < 256; c += 4) {
        float4 w4 = *(const float4*)(Wr + c);
#pragma unroll
        for (int px = 0; px < 32; px++) {
            float4 xv = *(const float4*)&xs[px * 256 + c];
            acc[px] += w4.x * xv.x + w4.y * xv.y + w4.z * xv.z + w4.w * xv.w;
        }
    }

    const float bias = bp[t];
#pragma unroll
    for (int px = 0; px < 32; px++)
        out[((size_t)(p0 + px) * NB + n) * CCH + t] = acc[px] + bias;
}

// ---------------------------------------------------------------------------
extern "C" void kernel_launch(void* const* d_in, const int* in_sizes, int n_in,
                              void* d_out, int out_size)
{
    const float* q     = (const float*)d_in[0];
    const float* k     = (const float*)d_in[1];
    const float* v     = (const float*)d_in[2];
    const float* WQ    = (const float*)d_in[3];
    const float* bQ    = (const float*)d_in[4];
    const float* WK    = (const float*)d_in[5];
    const float* bK    = (const float*)d_in[6];
    const float* WV    = (const float*)d_in[7];
    const float* bV    = (const float*)d_in[8];
    const float* Wrk   = (const float*)d_in[9];
    const float* brk   = (const float*)d_in[10];
    const float* rel_v = (const float*)d_in[11];
    const float* Wp    = (const float*)d_in[12];
    const float* bp    = (const float*)d_in[13];

    float* out = (float*)d_out;
    float* attn_out = nullptr;
    if (out_size >= OUT_ELEMS + ATTN_ELEMS)
        attn_out = out + OUT_ELEMS;

    cudaFuncSetAttribute(attn_kernel,
                         cudaFuncAttributeMaxDynamicSharedMemorySize, SMEM_BYTES);

    proj_kernel<<<dim3(64, 3), 256>>>(q, k, v, WQ, WK, WV, bQ, bK, bV);
    rvT_kernel<<<(HNUM * WS2 * HDim + 255) / 256, 256>>>(rel_v);
    attn_kernel<<<dim3(64, HNUM, NB), 256, SMEM_BYTES>>>(Wrk, brk, attn_out);
    final_kernel<<<64, 256>>>(Wp, bp, out);
}

// round 4
// speedup vs baseline: 1.2424x; 1.2424x over previous
#include <cuda_runtime.h>

// ---------------------------------------------------------------------------
// MultiheadLocalAttentionV1: N=2, C=256, H=8, HD=32, 32x32 spatial,
// 15x15 window (225 taps), dilation 1, pad 7.
// ---------------------------------------------------------------------------

#define NB      2
#define HNUM    8
#define HDim    32
#define CCH     256
#define WDIM    32
#define HW      1024
#define WS      15
#define WS2     225
#define MAXDIS  7

// attention tile: 8 wide x 4 tall = 32 pixels
#define TW      8
#define TH      4
#define TPIX    32
#define HR      (TH + 14)   // 18
#define HC      (TW + 14)   // 22
#define NHALO   (HR * HC)   // 396
#define KSTR    36          // halo row stride (floats), 16B-aligned rows
#define ASTR    244         // logits row stride: [15 kh][16 kw] padded + 4

#define T_CONST 5.656854249492381f
#define INV_T   0.17677669529663689f

#define OUT_ELEMS  (HW * NB * CCH)
#define ATTN_ELEMS (NB * HNUM * WS2 * HW)

// smem layout (floats)
#define S_K 0
#define S_A (NHALO * KSTR)                  // 14256
#define S_Q (S_A + TPIX * ASTR)             // + 7808 = 22064
#define SMEM_FLOATS (S_Q + TPIX * HDim)     // + 1024 = 23088
#define SMEM_BYTES  (SMEM_FLOATS * 4)       // 92352 B -> 2 CTAs/SM

// -------------------------- global scratch ---------------------------------
__device__ float g_qs[NB * HNUM * HW * HDim];
__device__ float g_kp[NB * HNUM * HW * HDim];
__device__ float g_vp[NB * HNUM * HW * HDim];
__device__ float g_ao[NB * HW * CCH];
__device__ float g_rvT[HNUM * WS2 * HDim];   // rel_v transposed (h,s,hd)

// ---------------------------------------------------------------------------
// K1: QKV projection. grid (128, 3): 16 pixels/block, 1 thread/out-channel.
// ---------------------------------------------------------------------------
__global__ __launch_bounds__(256) void proj_kernel(
    const float* __restrict__ q, const float* __restrict__ k, const float* __restrict__ v,
    const float* __restrict__ WQ, const float* __restrict__ WK, const float* __restrict__ WV,
    const float* __restrict__ bQ, const float* __restrict__ bK, const float* __restrict__ bV)
{
    __shared__ float xs[256 * 16];   // xs[c][px]

    const int m = blockIdx.y;
    const float* x = (m == 0) ? q : (m == 1) ? k : v;
    const float* W = (m == 0) ? WQ : (m == 1) ? WK : WV;
    const float* b = (m == 0) ? bQ : (m == 1) ? bK : bV;
    float* out     = (m == 0) ? g_qs : (m == 1) ? g_kp : g_vp;
    const float scale = (m == 0) ? INV_T : 1.0f;

    const int gp0 = blockIdx.x * 16;
    const int n   = gp0 >> 10;
    const int p0  = gp0 & 1023;
    const int t   = threadIdx.x;

    for (int idx = t; idx < 256 * 16; idx += 256) {
        int c = idx >> 4, px = idx & 15;
        xs[idx] = x[(n * 256 + c) * HW + p0 + px];
    }
    __syncthreads();

    float acc[16];
#pragma unroll
    for (int i = 0; i < 16; i++) acc[i] = 0.f;

    const float* Wr = W + t * 256;
    for (int c = 0; c < 256; c += 4) {
        float4 w4 = *(const float4*)(Wr + c);
        float wv[4] = {w4.x, w4.y, w4.z, w4.w};
#pragma unroll
        for (int j = 0; j < 4; j++) {
#pragma unroll
            for (int p4 = 0; p4 < 4; p4++) {
                float4 xv = *(const float4*)&xs[(c + j) * 16 + p4 * 4];
                acc[p4 * 4 + 0] += wv[j] * xv.x;
                acc[p4 * 4 + 1] += wv[j] * xv.y;
                acc[p4 * 4 + 2] += wv[j] * xv.z;
                acc[p4 * 4 + 3] += wv[j] * xv.w;
            }
        }
    }

    const float bias = b[t];
    const int h  = t >> 5;
    const int hd = t & 31;
    float* op = out + ((size_t)(n * HNUM + h) * HW) * HDim + hd;
#pragma unroll
    for (int px = 0; px < 16; px++)
        op[(size_t)(p0 + px) * HDim] = (acc[px] + bias) * scale;
}

// ---------------------------------------------------------------------------
// K2: transpose rel_v (H,HD,WS2) -> (H,WS2,HD)
// ---------------------------------------------------------------------------
__global__ void rvT_kernel(const float* __restrict__ rel_v)
{
    int i = blockIdx.x * 256 + threadIdx.x;
    if (i < HNUM * WS2 * HDim) {
        int c = i & 31;
        int s = (i >> 5) % WS2;
        int h = i / (WS2 * HDim);
        g_rvT[i] = rel_v[(h * HDim + c) * WS2 + s];
    }
}

// ---------------------------------------------------------------------------
// K3: local attention. grid = (32 tiles, 8 heads, 2 batch), 256 threads.
// ---------------------------------------------------------------------------
extern __shared__ float sm[];

__global__ __launch_bounds__(256) void attn_kernel(
    const float* __restrict__ Wrk, const float* __restrict__ brk,
    float* __restrict__ attn_out)
{
    const int h = blockIdx.y;
    const int n = blockIdx.z;
    const int tileIdx = blockIdx.x;
    const int tx0 = (tileIdx & 3) * TW;   // 4 tiles across
    const int ty0 = (tileIdx >> 2) * TH;  // 8 tiles down
    const int t = threadIdx.x;
    const int nh = n * HNUM + h;

    const float* qs = g_qs + (size_t)nh * HW * HDim;
    const float* kp = g_kp + (size_t)nh * HW * HDim;
    const float* vp = g_vp + (size_t)nh * HW * HDim;

    float* ksm  = sm + S_K;   // halo [NHALO][KSTR] (K then V)
    float* atsm = sm + S_A;   // logits/probs [TPIX][ASTR], [kh][16] inner
    float* qsm  = sm + S_Q;   // q tile [TPIX][32]; reused as partial buffer

    // ---- load q tile ----
    for (int idx = t; idx < TPIX * 32; idx += 256) {
        int px = idx >> 5, c = idx & 31;
        int gy = ty0 + (px >> 3), gx = tx0 + (px & 7);
        qsm[idx] = qs[(gy * WDIM + gx) * HDim + c];
    }
    // ---- load K halo (float4, zero padded) ----
    for (int i4 = t; i4 < NHALO * 8; i4 += 256) {
        int hp = i4 >> 3, c4 = (i4 & 7) * 4;
        int hy = hp / HC, hx = hp - hy * HC;
        int gy = ty0 - MAXDIS + hy, gx = tx0 - MAXDIS + hx;
        float4 vv = make_float4(0.f, 0.f, 0.f, 0.f);
        if ((unsigned)gy < 32u && (unsigned)gx < 32u)
            vv = *(const float4*)&kp[(gy * WDIM + gx) * HDim + c4];
        *(float4*)&ksm[hp * KSTR + c4] = vv;
    }
    __syncthreads();

    // ---- logits: thread = window tap s ----
    if (t < WS2) {
        const int s  = t;
        const int kh = s / WS;
        const int kw = s - kh * WS;
        float wreg[32];
#pragma unroll
        for (int c4 = 0; c4 < 32; c4 += 4) {
            float4 w4 = *(const float4*)&Wrk[(h * WS2 + s) * HDim + c4];
            wreg[c4]     = T_CONST * w4.x;
            wreg[c4 + 1] = T_CONST * w4.y;
            wreg[c4 + 2] = T_CONST * w4.z;
            wreg[c4 + 3] = T_CONST * w4.w;
        }
        const float bb = brk[h * WS2 + s];
        const int aoff = kh * 16 + kw;

#pragma unroll
        for (int py = 0; py < TH; py++) {
            const int gy = ty0 + py + kh - MAXDIS;
            const bool vy = ((unsigned)gy < 32u);
            const int hrow = (py + kh) * HC;
#pragma unroll
            for (int pxx = 0; pxx < TW; pxx++) {
                const int gx = tx0 + pxx + kw - MAXDIS;
                const float* kr = &ksm[(hrow + pxx + kw) * KSTR];
                const float* qr = &qsm[(py * TW + pxx) * 32];
                float a = bb;
#pragma unroll
                for (int c4 = 0; c4 < 32; c4 += 4) {
                    float4 qv = *(const float4*)(qr + c4);
                    float4 kv = *(const float4*)(kr + c4);
                    a += qv.x * kv.x + qv.y * kv.y + qv.z * kv.z + qv.w * kv.w;
                    a += qv.x * wreg[c4]     + qv.y * wreg[c4 + 1]
                       + qv.z * wreg[c4 + 2] + qv.w * wreg[c4 + 3];
                }
                if (!(vy && (unsigned)gx < 32u)) a -= 1e8f;
                atsm[(py * TW + pxx) * ASTR + aoff] = a;
            }
        }
    }
    __syncthreads();

    // ---- overwrite halo with V (overlaps softmax latency) ----
    for (int i4 = t; i4 < NHALO * 8; i4 += 256) {
        int hp = i4 >> 3, c4 = (i4 & 7) * 4;
        int hy = hp / HC, hx = hp - hy * HC;
        int gy = ty0 - MAXDIS + hy, gx = tx0 - MAXDIS + hx;
        float4 vv = make_float4(0.f, 0.f, 0.f, 0.f);
        if ((unsigned)gy < 32u && (unsigned)gx < 32u)
            vv = *(const float4*)&vp[(gy * WDIM + gx) * HDim + c4];
        *(float4*)&ksm[hp * KSTR + c4] = vv;
    }

    // ---- softmax: warp handles 4 pixels (padded [kh][16] layout) ----
    {
        const int warp = t >> 5, lane = t & 31;
#pragma unroll
        for (int pp = 0; pp < 4; pp++) {
            const int px = warp * 4 + pp;
            float* arow = &atsm[px * ASTR];
            // zero the kw=15 pad slots so output can't read garbage
            if (lane < 15) arow[lane * 16 + 15] = 0.f;
            float vals[8];
            int   offs[8];
            float mx = -3.4e38f;
#pragma unroll
            for (int i = 0; i < 8; i++) {
                int s = lane + 32 * i;
                if (s < WS2) {
                    offs[i] = (s / WS) * 16 + (s % WS);
                    vals[i] = arow[offs[i]];
                } else { offs[i] = -1; vals[i] = -3.4e38f; }
                mx = fmaxf(mx, vals[i]);
            }
#pragma unroll
            for (int off = 16; off; off >>= 1)
                mx = fmaxf(mx, __shfl_xor_sync(0xffffffffu, mx, off));
            float sum = 0.f;
#pragma unroll
            for (int i = 0; i < 8; i++) {
                float e = (offs[i] >= 0) ? __expf(vals[i] - mx) : 0.f;
                vals[i] = e;
                sum += e;
            }
#pragma unroll
            for (int off = 16; off; off >>= 1)
                sum += __shfl_xor_sync(0xffffffffu, sum, off);
            const float inv = 1.0f / sum;
#pragma unroll
            for (int i = 0; i < 8; i++)
                if (offs[i] >= 0) arow[offs[i]] = vals[i] * inv;
        }
    }
    __syncthreads();

    // ---- write attn probabilities (n,H,WS2,hw), coalesced over px ----
    if (attn_out) {
        float* ao = attn_out + (size_t)nh * WS2 * HW;
        for (int idx = t; idx < WS2 * TPIX; idx += 256) {
            int px = idx & 31, s = idx >> 5;
            int off = (s / WS) * 16 + (s % WS);
            int pgl = (ty0 + (px >> 3)) * WDIM + tx0 + (px & 7);
            ao[s * HW + pgl] = atsm[px * ASTR + off];
        }
    }

    // ---- output: sliding-window register scheme ----
    // warp w: py = w&3, half = w>>2 (kh 0..7 / 8..14). lane = channel.
    {
        const int c    = t & 31;
        const int warp = t >> 5;
        const int py   = warp & 3;
        const int half = warp >> 2;
        const int kh0  = half ? 8 : 0;
        const int kh1  = half ? 15 : 8;
        const float* rvh = g_rvT + (size_t)h * WS2 * HDim;

        float acc[TW];
#pragma unroll
        for (int i = 0; i < TW; i++) acc[i] = 0.f;

        for (int kh = kh0; kh < kh1; kh++) {
            const int hy = py + kh;
            float vreg[HC];
#pragma unroll
            for (int x = 0; x < HC; x++)
                vreg[x] = ksm[(hy * HC + x) * KSTR + c];
            float rreg[WS];
#pragma unroll
            for (int kw = 0; kw < WS; kw++)
                rreg[kw] = rvh[(kh * WS + kw) * HDim + c];

#pragma unroll
            for (int pxx = 0; pxx < TW; pxx++) {
                const float* arow = &atsm[(py * TW + pxx) * ASTR + kh * 16];
                float4 a0 = *(const float4*)(arow);
                float4 a1 = *(const float4*)(arow + 4);
                float4 a2 = *(const float4*)(arow + 8);
                float4 a3 = *(const float4*)(arow + 12);
                float av[15] = {a0.x, a0.y, a0.z, a0.w, a1.x, a1.y, a1.z, a1.w,
                                a2.x, a2.y, a2.z, a2.w, a3.x, a3.y, a3.z};
                float s0 = 0.f;
#pragma unroll
                for (int kw = 0; kw < WS; kw++) {
                    acc[pxx] += av[kw] * vreg[pxx + kw];
                    s0       += av[kw] * rreg[kw];
                }
                acc[pxx] += s0;
            }
        }

        // combine halves through smem (reuse qsm region)
        if (half == 1) {
#pragma unroll
            for (int pxx = 0; pxx < TW; pxx++)
                qsm[(py * TW + pxx) * 32 + c] = acc[pxx];
        }
        __syncthreads();
        if (half == 0) {
#pragma unroll
            for (int pxx = 0; pxx < TW; pxx++) {
                const int gy = ty0 + py, gx = tx0 + pxx;
                float tot = acc[pxx] + qsm[(py * TW + pxx) * 32 + c];
                g_ao[((size_t)n * HW + gy * WDIM + gx) * CCH + h * HDim + c] = tot;
            }
        }
    }
}

// ---------------------------------------------------------------------------
// K4: final projection. grid 128: 16 pixels/block, 1 thread/out-channel.
// ---------------------------------------------------------------------------
__global__ __launch_bounds__(256) void final_kernel(
    const float* __restrict__ Wp, const float* __restrict__ bp,
    float* __restrict__ out)
{
    __shared__ float xs[16 * 256];   // xs[px][c]

    const int gp0 = blockIdx.x * 16;
    const int n   = gp0 >> 10;
    const int p0  = gp0 & 1023;
    const int t   = threadIdx.x;

    const float* src = g_ao + ((size_t)n * HW + p0) * CCH;
    for (int idx = t; idx < 16 * 256; idx += 256)
        xs[idx] = src[idx];
    __syncthreads();

    float acc[16];
#pragma unroll
    for (int i = 0; i < 16; i++) acc[i] = 0.f;

    const float* Wr = Wp + t * 256;
    for (int c = 0; c < 256; c += 4) {
        float4 w4 = *(const float4*)(Wr + c);
#pragma unroll
        for (int px = 0; px < 16; px++) {
            float4 xv = *(const float4*)&xs[px * 256 + c];
            acc[px] += w4.x * xv.x + w4.y * xv.y + w4.z * xv.z + w4.w * xv.w;
        }
    }

    const float bias = bp[t];
#pragma unroll
    for (int px = 0; px < 16; px++)
        out[((size_t)(p0 + px) * NB + n) * CCH + t] = acc[px] + bias;
}

// ---------------------------------------------------------------------------
extern "C" void kernel_launch(void* const* d_in, const int* in_sizes, int n_in,
                              void* d_out, int out_size)
{
    const float* q     = (const float*)d_in[0];
    const float* k     = (const float*)d_in[1];
    const float* v     = (const float*)d_in[2];
    const float* WQ    = (const float*)d_in[3];
    const float* bQ    = (const float*)d_in[4];
    const float* WK    = (const float*)d_in[5];
    const float* bK    = (const float*)d_in[6];
    const float* WV    = (const float*)d_in[7];
    const float* bV    = (const float*)d_in[8];
    const float* Wrk   = (const float*)d_in[9];
    const float* brk   = (const float*)d_in[10];
    const float* rel_v = (const float*)d_in[11];
    const float* Wp    = (const float*)d_in[12];
    const float* bp    = (const float*)d_in[13];

    float* out = (float*)d_out;
    float* attn_out = nullptr;
    if (out_size >= OUT_ELEMS + ATTN_ELEMS)
        attn_out = out + OUT_ELEMS;

    cudaFuncSetAttribute(attn_kernel,
                         cudaFuncAttributeMaxDynamicSharedMemorySize, SMEM_BYTES);

    proj_kernel<<<dim3(128, 3), 256>>>(q, k, v, WQ, WK, WV, bQ, bK, bV);
    rvT_kernel<<<(HNUM * WS2 * HDim + 255) / 256, 256>>>(rel_v);
    attn_kernel<<<dim3(32, HNUM, NB), 256, SMEM_BYTES>>>(Wrk, brk, attn_out);
    final_kernel<<<128, 256>>>(Wp, bp, out);
}

// round 7
// speedup vs baseline: 1.5543x; 1.2510x over previous
#include <cuda_runtime.h>
#include <cstdint>

// ---------------------------------------------------------------------------
// MultiheadLocalAttentionV1: N=2, C=256, H=8, HD=32, 32x32 spatial,
// 15x15 window (225 taps), dilation 1, pad 7.
//
//   K1 proj_mma   : qp/kp/vp via tf32 tensor-core GEMM (3x-split, fp32 acc)
//   K2 rvT_kernel : transpose rel_v (H,HD,WS2) -> (H,WS2,HD)
//   K3 attn_kernel: local attention (fp32 SIMT, sliding-window output)
//   K4 final_mma  : out = ao @ Wp^T + bp via tf32 tensor-core GEMM
// ---------------------------------------------------------------------------

#define NB      2
#define HNUM    8
#define HDim    32
#define CCH     256
#define WDIM    32
#define HW      1024
#define WS      15
#define WS2     225
#define MAXDIS  7

#define TW      8
#define TH      4
#define TPIX    32
#define HR      (TH + 14)   // 18
#define HC      (TW + 14)   // 22
#define NHALO   (HR * HC)   // 396
#define KSTR    36
#define ASTR    244

#define T_CONST 5.656854249492381f
#define INV_T   0.17677669529663689f

#define OUT_ELEMS  (HW * NB * CCH)
#define ATTN_ELEMS (NB * HNUM * WS2 * HW)

// attn smem layout (floats)
#define S_K 0
#define S_A (NHALO * KSTR)
#define S_Q (S_A + TPIX * ASTR)
#define SMEM_FLOATS (S_Q + TPIX * HDim)
#define SMEM_BYTES  (SMEM_FLOATS * 4)       // 92352 B

// -------------------------- global scratch ---------------------------------
__device__ float g_qs[NB * HNUM * HW * HDim];
__device__ float g_kp[NB * HNUM * HW * HDim];
__device__ float g_vp[NB * HNUM * HW * HDim];
__device__ float g_ao[NB * HW * CCH];
__device__ float g_rvT[HNUM * WS2 * HDim];

// ---------------------------------------------------------------------------
// tf32 helpers
// ---------------------------------------------------------------------------
__device__ __forceinline__ uint32_t f2tf32(float x) {
    uint32_t r;
    asm("cvt.rna.tf32.f32 %0, %1;" : "=r"(r) : "f"(x));
    return r;
}
// split x into hi + lo, both tf32-rounded (3xTF32 scheme)
__device__ __forceinline__ void tf32_split(float x, float& hi, float& lo) {
    uint32_t h = f2tf32(x);
    hi = __uint_as_float(h);
    lo = __uint_as_float(f2tf32(x - hi));
}
__device__ __forceinline__ void mma_tf32(
    float& c0, float& c1, float& c2, float& c3,
    uint32_t a0, uint32_t a1, uint32_t a2, uint32_t a3,
    uint32_t b0, uint32_t b1)
{
    asm volatile(
        "mma.sync.aligned.m16n8k8.row.col.f32.tf32.tf32.f32 "
        "{%0,%1,%2,%3},{%4,%5,%6,%7},{%8,%9},{%0,%1,%2,%3};\n"
        : "+f"(c0), "+f"(c1), "+f"(c2), "+f"(c3)
        : "r"(a0), "r"(a1), "r"(a2), "r"(a3), "r"(b0), "r"(b1));
}

// GEMM tiling: block = 256 thr = 8 warps (2 m-warps x 4 n-warps)
// block tile 32m x 64n, warp tile 16m x 16n, BK = 32, K = 256
#define GSTR 36   // padded smem k-stride

// ---------------------------------------------------------------------------
// K1: QKV projection via tensor cores.
// grid (64 mtiles, 4 ntiles, 3 matrices), 256 threads.
// X[m][k]: m = n*1024+p, k = in-channel; input layout (n,c,p) -> strided.
// out = X @ W^T + b, scattered to (n,h,p,hd), q scaled by 1/T.
// ---------------------------------------------------------------------------
__global__ __launch_bounds__(256) void proj_mma(
    const float* __restrict__ q, const float* __restrict__ k, const float* __restrict__ v,
    const float* __restrict__ WQ, const float* __restrict__ WK, const float* __restrict__ WV,
    const float* __restrict__ bQ, const float* __restrict__ bK, const float* __restrict__ bV)
{
    __shared__ float xsh[32 * GSTR], xsl[32 * GSTR];
    __shared__ float wsh[64 * GSTR], wsl[64 * GSTR];

    const int m0  = blockIdx.x * 32;
    const int nc0 = blockIdx.y * 64;
    const int mat = blockIdx.z;

    const float* x = (mat == 0) ? q : (mat == 1) ? k : v;
    const float* W = (mat == 0) ? WQ : (mat == 1) ? WK : WV;
    const float* b = (mat == 0) ? bQ : (mat == 1) ? bK : bV;
    float* out     = (mat == 0) ? g_qs : (mat == 1) ? g_kp : g_vp;
    const float scale = (mat == 0) ? INV_T : 1.0f;

    const int n_b = m0 >> 10;
    const int p0  = m0 & 1023;

    const int t    = threadIdx.x;
    const int lane = t & 31;
    const int warp = t >> 5;
    const int wm   = warp & 1;        // m-warp (0..1)
    const int wn   = warp >> 1;       // n-warp (0..3)
    const int g    = lane >> 2;       // group id
    const int tig  = lane & 3;        // thread in group

    float acc[2][4];
#pragma unroll
    for (int i = 0; i < 2; i++)
#pragma unroll
        for (int j = 0; j < 4; j++) acc[i][j] = 0.f;

    for (int ks = 0; ks < 256; ks += 32) {
        // stage X slab: input is p-contiguous -> lanes over m, rows over c
        {
            const int dm = t & 31;
            const int cr = t >> 5;    // 8 c-rows per round
#pragma unroll
            for (int r = 0; r < 4; r++) {
                int kk = cr + r * 8;
                float vv = x[(size_t)(n_b * 256 + ks + kk) * HW + p0 + dm];
                float hi, lo; tf32_split(vv, hi, lo);
                xsh[dm * GSTR + kk] = hi;
                xsl[dm * GSTR + kk] = lo;
            }
        }
        // stage W slab: 64 rows x 32 k, coalesced
        {
#pragma unroll
            for (int r = 0; r < 8; r++) {
                int idx = r * 256 + t;
                int ol = idx >> 5, kk = idx & 31;
                float vv = W[(size_t)(nc0 + ol) * 256 + ks + kk];
                float hi, lo; tf32_split(vv, hi, lo);
                wsh[ol * GSTR + kk] = hi;
                wsl[ol * GSTR + kk] = lo;
            }
        }
        __syncthreads();

#pragma unroll
        for (int k8 = 0; k8 < 4; k8++) {
            const int kb = k8 * 8;
            const int ar0 = (wm * 16 + g) * GSTR + kb + tig;
            const int ar1 = (wm * 16 + 8 + g) * GSTR + kb + tig;
            uint32_t ah0 = __float_as_uint(xsh[ar0]);
            uint32_t ah1 = __float_as_uint(xsh[ar1]);
            uint32_t ah2 = __float_as_uint(xsh[ar0 + 4]);
            uint32_t ah3 = __float_as_uint(xsh[ar1 + 4]);
            uint32_t al0 = __float_as_uint(xsl[ar0]);
            uint32_t al1 = __float_as_uint(xsl[ar1]);
            uint32_t al2 = __float_as_uint(xsl[ar0 + 4]);
            uint32_t al3 = __float_as_uint(xsl[ar1 + 4]);
#pragma unroll
            for (int nt = 0; nt < 2; nt++) {
                const int br = (wn * 16 + nt * 8 + g) * GSTR + kb + tig;
                uint32_t bh0 = __float_as_uint(wsh[br]);
                uint32_t bh1 = __float_as_uint(wsh[br + 4]);
                uint32_t bl0 = __float_as_uint(wsl[br]);
                uint32_t bl1 = __float_as_uint(wsl[br + 4]);
                mma_tf32(acc[nt][0], acc[nt][1], acc[nt][2], acc[nt][3],
                         ah0, ah1, ah2, ah3, bh0, bh1);
                mma_tf32(acc[nt][0], acc[nt][1], acc[nt][2], acc[nt][3],
                         ah0, ah1, ah2, ah3, bl0, bl1);
                mma_tf32(acc[nt][0], acc[nt][1], acc[nt][2], acc[nt][3],
                         al0, al1, al2, al3, bh0, bh1);
            }
        }
        __syncthreads();
    }

    // epilogue: scatter to (n,h,p,hd) with bias + scale
#pragma unroll
    for (int nt = 0; nt < 2; nt++) {
        const int o  = nc0 + wn * 16 + nt * 8 + 2 * tig;
        const int h  = o >> 5, hd = o & 31;
        const float b0v = b[o], b1v = b[o + 1];
        const int r0 = wm * 16 + g;
        float* base = out + ((size_t)(n_b * HNUM + h) * HW) * HDim + hd;
        base[(size_t)(p0 + r0) * HDim]         = (acc[nt][0] + b0v) * scale;
        base[(size_t)(p0 + r0) * HDim + 1]     = (acc[nt][1] + b1v) * scale;
        base[(size_t)(p0 + r0 + 8) * HDim]     = (acc[nt][2] + b0v) * scale;
        base[(size_t)(p0 + r0 + 8) * HDim + 1] = (acc[nt][3] + b1v) * scale;
    }
}

// ---------------------------------------------------------------------------
// K2: transpose rel_v (H,HD,WS2) -> (H,WS2,HD)
// ---------------------------------------------------------------------------
__global__ void rvT_kernel(const float* __restrict__ rel_v)
{
    int i = blockIdx.x * 256 + threadIdx.x;
    if (i < HNUM * WS2 * HDim) {
        int c = i & 31;
        int s = (i >> 5) % WS2;
        int h = i / (WS2 * HDim);
        g_rvT[i] = rel_v[(h * HDim + c) * WS2 + s];
    }
}

// ---------------------------------------------------------------------------
// K3: local attention. grid = (32 tiles, 8 heads, 2 batch), 256 threads.
// ---------------------------------------------------------------------------
extern __shared__ float sm[];

__global__ __launch_bounds__(256) void attn_kernel(
    const float* __restrict__ Wrk, const float* __restrict__ brk,
    float* __restrict__ attn_out)
{
    const int h = blockIdx.y;
    const int n = blockIdx.z;
    const int tileIdx = blockIdx.x;
    const int tx0 = (tileIdx & 3) * TW;
    const int ty0 = (tileIdx >> 2) * TH;
    const int t = threadIdx.x;
    const int nh = n * HNUM + h;

    const float* qs = g_qs + (size_t)nh * HW * HDim;
    const float* kp = g_kp + (size_t)nh * HW * HDim;
    const float* vp = g_vp + (size_t)nh * HW * HDim;

    float* ksm  = sm + S_K;
    float* atsm = sm + S_A;
    float* qsm  = sm + S_Q;

    for (int idx = t; idx < TPIX * 32; idx += 256) {
        int px = idx >> 5, c = idx & 31;
        int gy = ty0 + (px >> 3), gx = tx0 + (px & 7);
        qsm[idx] = qs[(gy * WDIM + gx) * HDim + c];
    }
    for (int i4 = t; i4 < NHALO * 8; i4 += 256) {
        int hp = i4 >> 3, c4 = (i4 & 7) * 4;
        int hy = hp / HC, hx = hp - hy * HC;
        int gy = ty0 - MAXDIS + hy, gx = tx0 - MAXDIS + hx;
        float4 vv = make_float4(0.f, 0.f, 0.f, 0.f);
        if ((unsigned)gy < 32u && (unsigned)gx < 32u)
            vv = *(const float4*)&kp[(gy * WDIM + gx) * HDim + c4];
        *(float4*)&ksm[hp * KSTR + c4] = vv;
    }
    __syncthreads();

    if (t < WS2) {
        const int s  = t;
        const int kh = s / WS;
        const int kw = s - kh * WS;
        float wreg[32];
#pragma unroll
        for (int c4 = 0; c4 < 32; c4 += 4) {
            float4 w4 = *(const float4*)&Wrk[(h * WS2 + s) * HDim + c4];
            wreg[c4]     = T_CONST * w4.x;
            wreg[c4 + 1] = T_CONST * w4.y;
            wreg[c4 + 2] = T_CONST * w4.z;
            wreg[c4 + 3] = T_CONST * w4.w;
        }
        const float bb = brk[h * WS2 + s];
        const int aoff = kh * 16 + kw;

#pragma unroll
        for (int py = 0; py < TH; py++) {
            const int gy = ty0 + py + kh - MAXDIS;
            const bool vy = ((unsigned)gy < 32u);
            const int hrow = (py + kh) * HC;
#pragma unroll
            for (int pxx = 0; pxx < TW; pxx++) {
                const int gx = tx0 + pxx + kw - MAXDIS;
                const float* kr = &ksm[(hrow + pxx + kw) * KSTR];
                const float* qr = &qsm[(py * TW + pxx) * 32];
                float a = bb;
#pragma unroll
                for (int c4 = 0; c4 < 32; c4 += 4) {
                    float4 qv = *(const float4*)(qr + c4);
                    float4 kv = *(const float4*)(kr + c4);
                    a += qv.x * kv.x + qv.y * kv.y + qv.z * kv.z + qv.w * kv.w;
                    a += qv.x * wreg[c4]     + qv.y * wreg[c4 + 1]
                       + qv.z * wreg[c4 + 2] + qv.w * wreg[c4 + 3];
                }
                if (!(vy && (unsigned)gx < 32u)) a -= 1e8f;
                atsm[(py * TW + pxx) * ASTR + aoff] = a;
            }
        }
    }
    __syncthreads();

    for (int i4 = t; i4 < NHALO * 8; i4 += 256) {
        int hp = i4 >> 3, c4 = (i4 & 7) * 4;
        int hy = hp / HC, hx = hp - hy * HC;
        int gy = ty0 - MAXDIS + hy, gx = tx0 - MAXDIS + hx;
        float4 vv = make_float4(0.f, 0.f, 0.f, 0.f);
        if ((unsigned)gy < 32u && (unsigned)gx < 32u)
            vv = *(const float4*)&vp[(gy * WDIM + gx) * HDim + c4];
        *(float4*)&ksm[hp * KSTR + c4] = vv;
    }

    {
        const int warp = t >> 5, lane = t & 31;
#pragma unroll
        for (int pp = 0; pp < 4; pp++) {
            const int px = warp * 4 + pp;
            float* arow = &atsm[px * ASTR];
            if (lane < 15) arow[lane * 16 + 15] = 0.f;
            float vals[8];
            int   offs[8];
            float mx = -3.4e38f;
#pragma unroll
            for (int i = 0; i < 8; i++) {
                int s = lane + 32 * i;
                if (s < WS2) {
                    offs[i] = (s / WS) * 16 + (s % WS);
                    vals[i] = arow[offs[i]];
                } else { offs[i] = -1; vals[i] = -3.4e38f; }
                mx = fmaxf(mx, vals[i]);
            }
#pragma unroll
            for (int off = 16; off; off >>= 1)
                mx = fmaxf(mx, __shfl_xor_sync(0xffffffffu, mx, off));
            float sum = 0.f;
#pragma unroll
            for (int i = 0; i < 8; i++) {
                float e = (offs[i] >= 0) ? __expf(vals[i] - mx) : 0.f;
                vals[i] = e;
                sum += e;
            }
#pragma unroll
            for (int off = 16; off; off >>= 1)
                sum += __shfl_xor_sync(0xffffffffu, sum, off);
            const float inv = 1.0f / sum;
#pragma unroll
            for (int i = 0; i < 8; i++)
                if (offs[i] >= 0) arow[offs[i]] = vals[i] * inv;
        }
    }
    __syncthreads();

    if (attn_out) {
        float* ao = attn_out + (size_t)nh * WS2 * HW;
        for (int idx = t; idx < WS2 * TPIX; idx += 256) {
            int px = idx & 31, s = idx >> 5;
            int off = (s / WS) * 16 + (s % WS);
            int pgl = (ty0 + (px >> 3)) * WDIM + tx0 + (px & 7);
            ao[s * HW + pgl] = atsm[px * ASTR + off];
        }
    }

    {
        const int c    = t & 31;
        const int warp = t >> 5;
        const int py   = warp & 3;
        const int half = warp >> 2;
        const int kh0  = half ? 8 : 0;
        const int kh1  = half ? 15 : 8;
        const float* rvh = g_rvT + (size_t)h * WS2 * HDim;

        float acc[TW];
#pragma unroll
        for (int i = 0; i < TW; i++) acc[i] = 0.f;

        for (int kh = kh0; kh < kh1; kh++) {
            const int hy = py + kh;
            float vreg[HC];
#pragma unroll
            for (int x = 0; x < HC; x++)
                vreg[x] = ksm[(hy * HC + x) * KSTR + c];
            float rreg[WS];
#pragma unroll
            for (int kw = 0; kw < WS; kw++)
                rreg[kw] = rvh[(kh * WS + kw) * HDim + c];

#pragma unroll
            for (int pxx = 0; pxx < TW; pxx++) {
                const float* arow = &atsm[(py * TW + pxx) * ASTR + kh * 16];
                float4 a0 = *(const float4*)(arow);
                float4 a1 = *(const float4*)(arow + 4);
                float4 a2 = *(const float4*)(arow + 8);
                float4 a3 = *(const float4*)(arow + 12);
                float av[15] = {a0.x, a0.y, a0.z, a0.w, a1.x, a1.y, a1.z, a1.w,
                                a2.x, a2.y, a2.z, a2.w, a3.x, a3.y, a3.z};
                float s0 = 0.f;
#pragma unroll
                for (int kw = 0; kw < WS; kw++) {
                    acc[pxx] += av[kw] * vreg[pxx + kw];
                    s0       += av[kw] * rreg[kw];
                }
                acc[pxx] += s0;
            }
        }

        if (half == 1) {
#pragma unroll
            for (int pxx = 0; pxx < TW; pxx++)
                qsm[(py * TW + pxx) * 32 + c] = acc[pxx];
        }
        __syncthreads();
        if (half == 0) {
#pragma unroll
            for (int pxx = 0; pxx < TW; pxx++) {
                const int gy = ty0 + py, gx = tx0 + pxx;
                float tot = acc[pxx] + qsm[(py * TW + pxx) * 32 + c];
                g_ao[((size_t)n * HW + gy * WDIM + gx) * CCH + h * HDim + c] = tot;
            }
        }
    }
}

// ---------------------------------------------------------------------------
// K4: final projection via tensor cores. grid (64 mtiles, 4 ntiles).
// X = g_ao row-major [2048][256]. out[(p*NB+n)*256+o] = X@Wp^T + bp.
// ---------------------------------------------------------------------------
__global__ __launch_bounds__(256) void final_mma(
    const float* __restrict__ Wp, const float* __restrict__ bp,
    float* __restrict__ out)
{
    __shared__ float xsh[32 * GSTR], xsl[32 * GSTR];
    __shared__ float wsh[64 * GSTR], wsl[64 * GSTR];

    const int m0  = blockIdx.x * 32;
    const int nc0 = blockIdx.y * 64;

    const int t    = threadIdx.x;
    const int lane = t & 31;
    const int warp = t >> 5;
    const int wm   = warp & 1;
    const int wn   = warp >> 1;
    const int g    = lane >> 2;
    const int tig  = lane & 3;

    float acc[2][4];
#pragma unroll
    for (int i = 0; i < 2; i++)
#pragma unroll
        for (int j = 0; j < 4; j++) acc[i][j] = 0.f;

    for (int ks = 0; ks < 256; ks += 32) {
        // stage X slab (row-major, coalesced along k)
#pragma unroll
        for (int r = 0; r < 4; r++) {
            int idx = r * 256 + t;
            int ml = idx >> 5, kk = idx & 31;
            float vv = g_ao[(size_t)(m0 + ml) * 256 + ks + kk];
            float hi, lo; tf32_split(vv, hi, lo);
            xsh[ml * GSTR + kk] = hi;
            xsl[ml * GSTR + kk] = lo;
        }
        // stage W slab
#pragma unroll
        for (int r = 0; r < 8; r++) {
            int idx = r * 256 + t;
            int ol = idx >> 5, kk = idx & 31;
            float vv = Wp[(size_t)(nc0 + ol) * 256 + ks + kk];
            float hi, lo; tf32_split(vv, hi, lo);
            wsh[ol * GSTR + kk] = hi;
            wsl[ol * GSTR + kk] = lo;
        }
        __syncthreads();

#pragma unroll
        for (int k8 = 0; k8 < 4; k8++) {
            const int kb = k8 * 8;
            const int ar0 = (wm * 16 + g) * GSTR + kb + tig;
            const int ar1 = (wm * 16 + 8 + g) * GSTR + kb + tig;
            uint32_t ah0 = __float_as_uint(xsh[ar0]);
            uint32_t ah1 = __float_as_uint(xsh[ar1]);
            uint32_t ah2 = __float_as_uint(xsh[ar0 + 4]);
            uint32_t ah3 = __float_as_uint(xsh[ar1 + 4]);
            uint32_t al0 = __float_as_uint(xsl[ar0]);
            uint32_t al1 = __float_as_uint(xsl[ar1]);
            uint32_t al2 = __float_as_uint(xsl[ar0 + 4]);
            uint32_t al3 = __float_as_uint(xsl[ar1 + 4]);
#pragma unroll
            for (int nt = 0; nt < 2; nt++) {
                const int br = (wn * 16 + nt * 8 + g) * GSTR + kb + tig;
                uint32_t bh0 = __float_as_uint(wsh[br]);
                uint32_t bh1 = __float_as_uint(wsh[br + 4]);
                uint32_t bl0 = __float_as_uint(wsl[br]);
                uint32_t bl1 = __float_as_uint(wsl[br + 4]);
                mma_tf32(acc[nt][0], acc[nt][1], acc[nt][2], acc[nt][3],
                         ah0, ah1, ah2, ah3, bh0, bh1);
                mma_tf32(acc[nt][0], acc[nt][1], acc[nt][2], acc[nt][3],
                         ah0, ah1, ah2, ah3, bl0, bl1);
                mma_tf32(acc[nt][0], acc[nt][1], acc[nt][2], acc[nt][3],
                         al0, al1, al2, al3, bh0, bh1);
            }
        }
        __syncthreads();
    }

    // epilogue: out[(p*NB + n)*256 + o]
#pragma unroll
    for (int nt = 0; nt < 2; nt++) {
        const int o = nc0 + wn * 16 + nt * 8 + 2 * tig;
        const float b0v = bp[o], b1v = bp[o + 1];
#pragma unroll
        for (int rr = 0; rr < 2; rr++) {
            const int m = m0 + wm * 16 + g + rr * 8;
            const int n = m >> 10, p = m & 1023;
            float* op = out + ((size_t)p * NB + n) * CCH + o;
            op[0] = acc[nt][rr * 2]     + b0v;
            op[1] = acc[nt][rr * 2 + 1] + b1v;
        }
    }
}

// ---------------------------------------------------------------------------
extern "C" void kernel_launch(void* const* d_in, const int* in_sizes, int n_in,
                              void* d_out, int out_size)
{
    const float* q     = (const float*)d_in[0];
    const float* k     = (const float*)d_in[1];
    const float* v     = (const float*)d_in[2];
    const float* WQ    = (const float*)d_in[3];
    const float* bQ    = (const float*)d_in[4];
    const float* WK    = (const float*)d_in[5];
    const float* bK    = (const float*)d_in[6];
    const float* WV    = (const float*)d_in[7];
    const float* bV    = (const float*)d_in[8];
    const float* Wrk   = (const float*)d_in[9];
    const float* brk   = (const float*)d_in[10];
    const float* rel_v = (const float*)d_in[11];
    const float* Wp    = (const float*)d_in[12];
    const float* bp    = (const float*)d_in[13];

    float* out = (float*)d_out;
    float* attn_out = nullptr;
    if (out_size >= OUT_ELEMS + ATTN_ELEMS)
        attn_out = out + OUT_ELEMS;

    cudaFuncSetAttribute(attn_kernel,
                         cudaFuncAttributeMaxDynamicSharedMemorySize, SMEM_BYTES);

    proj_mma<<<dim3(64, 4, 3), 256>>>(q, k, v, WQ, WK, WV, bQ, bK, bV);
    rvT_kernel<<<(HNUM * WS2 * HDim + 255) / 256, 256>>>(rel_v);
    attn_kernel<<<dim3(32, HNUM, NB), 256, SMEM_BYTES>>>(Wrk, brk, attn_out);
    final_mma<<<dim3(64, 4), 256>>>(Wp, bp, out);
}

// round 8
// speedup vs baseline: 1.7640x; 1.1349x over previous
#include <cuda_runtime.h>
#include <cuda_bf16.h>
#include <cstdint>

// ---------------------------------------------------------------------------
// MultiheadLocalAttentionV1: N=2, C=256, H=8, HD=32, 32x32 spatial,
// 15x15 window (225 taps), dilation 1, pad 7.
//
//   prep_w     : split 4 weight mats into bf16 hi/lo, B-fragment layout
//   prep_qkv   : split q/k/v activations into bf16 hi/lo, A-fragment layout
//   proj_gemm  : qp/kp/vp = X@W^T + b via bf16 mma (2-way split, fp32 acc)
//   rvT_kernel : transpose rel_v (H,HD,WS2) -> (H,WS2,HD)
//   attn_kernel: local attention (fp32 SIMT, sliding-window output)
//   prep_ao    : split attention output into A-fragment layout
//   final_gemm : out = ao @ Wp^T + bp
// ---------------------------------------------------------------------------

#define NB      2
#define HNUM    8
#define HDim    32
#define CCH     256
#define WDIM    32
#define HW      1024
#define WS      15
#define WS2     225
#define MAXDIS  7

#define TW      8
#define TH      4
#define TPIX    32
#define HR      (TH + 14)   // 18
#define HC      (TW + 14)   // 22
#define NHALO   (HR * HC)   // 396
#define KSTR    36
#define ASTR    244

#define T_CONST 5.656854249492381f
#define INV_T   0.17677669529663689f

#define OUT_ELEMS  (HW * NB * CCH)
#define ATTN_ELEMS (NB * HNUM * WS2 * HW)

// attn smem layout (floats)
#define S_K 0
#define S_A (NHALO * KSTR)
#define S_Q (S_A + TPIX * ASTR)
#define SMEM_FLOATS (S_Q + TPIX * HDim)
#define SMEM_BYTES  (SMEM_FLOATS * 4)       // 92352 B

// fragment-array sizes
#define AFRAGS  65536   // per matrix: 128 m16 x 16 k16 x 32 lanes (uint4)
#define BFRAGS  16384   // per matrix: 32 n8 x 16 k16 x 32 lanes (uint2)

// -------------------------- global scratch ---------------------------------
__device__ float g_qs[NB * HNUM * HW * HDim];
__device__ float g_kp[NB * HNUM * HW * HDim];
__device__ float g_vp[NB * HNUM * HW * HDim];
__device__ float g_ao[NB * HW * CCH];
__device__ float g_rvT[HNUM * WS2 * HDim];

__device__ uint4 g_Ahi[4 * AFRAGS];   // slots: 0=q 1=k 2=v 3=ao
__device__ uint4 g_Alo[4 * AFRAGS];
__device__ uint2 g_Bhi[4 * BFRAGS];   // slots: 0=WQ 1=WK 2=WV 3=Wp
__device__ uint2 g_Blo[4 * BFRAGS];

// ---------------------------------------------------------------------------
// bf16 helpers
// ---------------------------------------------------------------------------
__device__ __forceinline__ uint32_t pack2(float even_k, float odd_k) {
    __nv_bfloat162 t = __floats2bfloat162_rn(even_k, odd_k);  // .x = low half
    return *reinterpret_cast<uint32_t*>(&t);
}
__device__ __forceinline__ void split1(float x, float& hi, float& lo) {
    hi = __bfloat162float(__float2bfloat16(x));
    lo = x - hi;
}
__device__ __forceinline__ void mma_bf16(float* acc, uint4 a, uint2 b) {
    asm volatile(
        "mma.sync.aligned.m16n8k16.row.col.f32.bf16.bf16.f32 "
        "{%0,%1,%2,%3},{%4,%5,%6,%7},{%8,%9},{%0,%1,%2,%3};\n"
        : "+f"(acc[0]), "+f"(acc[1]), "+f"(acc[2]), "+f"(acc[3])
        : "r"(a.x), "r"(a.y), "r"(a.z), "r"(a.w), "r"(b.x), "r"(b.y));
}

// ---------------------------------------------------------------------------
// prep_w: split WQ/WK/WV/Wp into B-fragment layout.
// thread = (mat, n8, k16, lane). b0 = W[n8*8+g][kb], [kb+1]; b1 = [kb+8], [kb+9]
// ---------------------------------------------------------------------------
__global__ __launch_bounds__(256) void prep_w(
    const float* __restrict__ WQ, const float* __restrict__ WK,
    const float* __restrict__ WV, const float* __restrict__ Wp)
{
    int tid  = blockIdx.x * 256 + threadIdx.x;   // 65536 total
    int lane = tid & 31;
    int k16  = (tid >> 5) & 15;
    int n8   = (tid >> 9) & 31;
    int mat  = tid >> 14;
    const float* W = (mat == 0) ? WQ : (mat == 1) ? WK : (mat == 2) ? WV : Wp;

    int g = lane >> 2, tig = lane & 3;
    int n  = n8 * 8 + g;
    int kb = k16 * 16 + 2 * tig;

    const float* r = W + (size_t)n * 256;
    float h0, l0, h1, l1, h8, l8, h9, l9;
    split1(r[kb],     h0, l0);
    split1(r[kb + 1], h1, l1);
    split1(r[kb + 8], h8, l8);
    split1(r[kb + 9], h9, l9);

    size_t idx = ((size_t)(mat * 32 + n8) * 16 + k16) * 32 + lane;
    g_Bhi[idx] = make_uint2(pack2(h0, h1), pack2(h8, h9));
    g_Blo[idx] = make_uint2(pack2(l0, l1), pack2(l8, l9));
}

// ---------------------------------------------------------------------------
// prep_qkv: split q/k/v into A-fragment layout (X[m][k] = src[(n*256+k)*1024+p])
// thread = (m16, k16, lane). a0=(r0,kb..kb+1) a1=(r1,..) a2=(r0,kb+8..) a3=(r1,..)
// ---------------------------------------------------------------------------
__global__ __launch_bounds__(256) void prep_qkv(
    const float* __restrict__ q, const float* __restrict__ k,
    const float* __restrict__ v)
{
    int mat = blockIdx.y;
    const float* src = (mat == 0) ? q : (mat == 1) ? k : v;

    int tid  = blockIdx.x * 256 + threadIdx.x;   // 65536
    int lane = tid & 31;
    int k16  = (tid >> 5) & 15;
    int m16  = tid >> 9;
    int g = lane >> 2, tig = lane & 3;
    int r0 = m16 * 16 + g;
    int r1 = r0 + 8;
    int kb = k16 * 16 + 2 * tig;

    int n0 = r0 >> 10, p0 = r0 & 1023;
    int n1 = r1 >> 10, p1 = r1 & 1023;

    uint32_t hi[4], lo[4];
#pragma unroll
    for (int j = 0; j < 4; j++) {
        int row_n = (j & 1) ? n1 : n0;
        int row_p = (j & 1) ? p1 : p0;
        int kc = kb + ((j >> 1) ? 8 : 0);
        float f0 = src[((size_t)(row_n * 256 + kc)) * 1024 + row_p];
        float f1 = src[((size_t)(row_n * 256 + kc + 1)) * 1024 + row_p];
        float h0, l0, h1, l1;
        split1(f0, h0, l0);
        split1(f1, h1, l1);
        hi[j] = pack2(h0, h1);
        lo[j] = pack2(l0, l1);
    }
    size_t idx = (size_t)mat * AFRAGS + ((size_t)m16 * 16 + k16) * 32 + lane;
    g_Ahi[idx] = make_uint4(hi[0], hi[1], hi[2], hi[3]);
    g_Alo[idx] = make_uint4(lo[0], lo[1], lo[2], lo[3]);
}

// ---------------------------------------------------------------------------
// prep_ao: split g_ao (row-major [2048][256]) into A-fragment slot 3.
// ---------------------------------------------------------------------------
__global__ __launch_bounds__(256) void prep_ao()
{
    int tid  = blockIdx.x * 256 + threadIdx.x;   // 65536
    int lane = tid & 31;
    int k16  = (tid >> 5) & 15;
    int m16  = tid >> 9;
    int g = lane >> 2, tig = lane & 3;
    int r0 = m16 * 16 + g;
    int kb = k16 * 16 + 2 * tig;

    uint32_t hi[4], lo[4];
#pragma unroll
    for (int j = 0; j < 4; j++) {
        int row = r0 + ((j & 1) ? 8 : 0);
        int kc  = kb + ((j >> 1) ? 8 : 0);
        float2 f = *(const float2*)&g_ao[(size_t)row * 256 + kc];
        float h0, l0, h1, l1;
        split1(f.x, h0, l0);
        split1(f.y, h1, l1);
        hi[j] = pack2(h0, h1);
        lo[j] = pack2(l0, l1);
    }
    size_t idx = (size_t)3 * AFRAGS + ((size_t)m16 * 16 + k16) * 32 + lane;
    g_Ahi[idx] = make_uint4(hi[0], hi[1], hi[2], hi[3]);
    g_Alo[idx] = make_uint4(lo[0], lo[1], lo[2], lo[3]);
}

// ---------------------------------------------------------------------------
// GEMM core: warp computes 16m x 32n over K=256. No smem.
// ---------------------------------------------------------------------------
__device__ __forceinline__ void gemm_core(
    const uint4* __restrict__ Ahi, const uint4* __restrict__ Alo,
    const uint2* __restrict__ Bhi, const uint2* __restrict__ Blo,
    int m16, int n8b, int lane, float acc[4][4])
{
#pragma unroll 4
    for (int k16 = 0; k16 < 16; k16++) {
        uint4 ah = Ahi[((size_t)m16 * 16 + k16) * 32 + lane];
        uint4 al = Alo[((size_t)m16 * 16 + k16) * 32 + lane];
#pragma unroll
        for (int nt = 0; nt < 4; nt++) {
            size_t bi = ((size_t)(n8b + nt) * 16 + k16) * 32 + lane;
            uint2 bh = Bhi[bi];
            uint2 bl = Blo[bi];
            mma_bf16(acc[nt], ah, bh);
            mma_bf16(acc[nt], ah, bl);
            mma_bf16(acc[nt], al, bh);
        }
    }
}

// ---------------------------------------------------------------------------
// proj_gemm: grid (32 m-blocks, 8 n-blocks, 3 mats), 128 threads (4 warps).
// Writes (n,h,p,hd); q scaled by 1/T.
// ---------------------------------------------------------------------------
__global__ __launch_bounds__(128) void proj_gemm(
    const float* __restrict__ bQ, const float* __restrict__ bK,
    const float* __restrict__ bV)
{
    const int mat  = blockIdx.z;
    const int warp = threadIdx.x >> 5;
    const int lane = threadIdx.x & 31;
    const int m16  = blockIdx.x * 4 + warp;
    const int n8b  = blockIdx.y * 4;

    const uint4* Ahi = g_Ahi + (size_t)mat * AFRAGS;
    const uint4* Alo = g_Alo + (size_t)mat * AFRAGS;
    const uint2* Bhi = g_Bhi + (size_t)mat * BFRAGS;
    const uint2* Blo = g_Blo + (size_t)mat * BFRAGS;

    float acc[4][4];
#pragma unroll
    for (int i = 0; i < 4; i++)
#pragma unroll
        for (int j = 0; j < 4; j++) acc[i][j] = 0.f;

    gemm_core(Ahi, Alo, Bhi, Blo, m16, n8b, lane, acc);

    const float* b = (mat == 0) ? bQ : (mat == 1) ? bK : bV;
    float* out     = (mat == 0) ? g_qs : (mat == 1) ? g_kp : g_vp;
    const float scale = (mat == 0) ? INV_T : 1.0f;

    const int g = lane >> 2, tig = lane & 3;
    const int r0 = m16 * 16 + g;
#pragma unroll
    for (int nt = 0; nt < 4; nt++) {
        const int o0 = (n8b + nt) * 8 + 2 * tig;
        const int h = o0 >> 5, hd = o0 & 31;
        const float b0 = b[o0], b1 = b[o0 + 1];
#pragma unroll
        for (int rr = 0; rr < 2; rr++) {
            const int r = r0 + rr * 8;
            const int n_b = r >> 10, p = r & 1023;
            float2 val;
            val.x = (acc[nt][rr * 2]     + b0) * scale;
            val.y = (acc[nt][rr * 2 + 1] + b1) * scale;
            *(float2*)&out[((size_t)(n_b * HNUM + h) * HW + p) * HDim + hd] = val;
        }
    }
}

// ---------------------------------------------------------------------------
// final_gemm: grid (32, 8), 128 threads. out[(p*NB+n)*256+o] = ao@Wp^T + bp
// ---------------------------------------------------------------------------
__global__ __launch_bounds__(128) void final_gemm(
    const float* __restrict__ bp, float* __restrict__ out)
{
    const int warp = threadIdx.x >> 5;
    const int lane = threadIdx.x & 31;
    const int m16  = blockIdx.x * 4 + warp;
    const int n8b  = blockIdx.y * 4;

    const uint4* Ahi = g_Ahi + (size_t)3 * AFRAGS;
    const uint4* Alo = g_Alo + (size_t)3 * AFRAGS;
    const uint2* Bhi = g_Bhi + (size_t)3 * BFRAGS;
    const uint2* Blo = g_Blo + (size_t)3 * BFRAGS;

    float acc[4][4];
#pragma unroll
    for (int i = 0; i < 4; i++)
#pragma unroll
        for (int j = 0; j < 4; j++) acc[i][j] = 0.f;

    gemm_core(Ahi, Alo, Bhi, Blo, m16, n8b, lane, acc);

    const int g = lane >> 2, tig = lane & 3;
    const int r0 = m16 * 16 + g;
#pragma unroll
    for (int nt = 0; nt < 4; nt++) {
        const int o0 = (n8b + nt) * 8 + 2 * tig;
        const float b0 = bp[o0], b1 = bp[o0 + 1];
#pragma unroll
        for (int rr = 0; rr < 2; rr++) {
            const int r = r0 + rr * 8;
            const int n_b = r >> 10, p = r & 1023;
            float2 val;
            val.x = acc[nt][rr * 2]     + b0;
            val.y = acc[nt][rr * 2 + 1] + b1;
            *(float2*)&out[((size_t)p * NB + n_b) * CCH + o0] = val;
        }
    }
}

// ---------------------------------------------------------------------------
// rvT: transpose rel_v (H,HD,WS2) -> (H,WS2,HD)
// ---------------------------------------------------------------------------
__global__ void rvT_kernel(const float* __restrict__ rel_v)
{
    int i = blockIdx.x * 256 + threadIdx.x;
    if (i < HNUM * WS2 * HDim) {
        int c = i & 31;
        int s = (i >> 5) % WS2;
        int h = i / (WS2 * HDim);
        g_rvT[i] = rel_v[(h * HDim + c) * WS2 + s];
    }
}

// ---------------------------------------------------------------------------
// attn_kernel: local attention. grid = (32 tiles, 8 heads, 2 batch), 256 thr.
// ---------------------------------------------------------------------------
extern __shared__ float sm[];

__global__ __launch_bounds__(256) void attn_kernel(
    const float* __restrict__ Wrk, const float* __restrict__ brk,
    float* __restrict__ attn_out)
{
    const int h = blockIdx.y;
    const int n = blockIdx.z;
    const int tileIdx = blockIdx.x;
    const int tx0 = (tileIdx & 3) * TW;
    const int ty0 = (tileIdx >> 2) * TH;
    const int t = threadIdx.x;
    const int nh = n * HNUM + h;

    const float* qs = g_qs + (size_t)nh * HW * HDim;
    const float* kp = g_kp + (size_t)nh * HW * HDim;
    const float* vp = g_vp + (size_t)nh * HW * HDim;

    float* ksm  = sm + S_K;
    float* atsm = sm + S_A;
    float* qsm  = sm + S_Q;

    for (int idx = t; idx < TPIX * 32; idx += 256) {
        int px = idx >> 5, c = idx & 31;
        int gy = ty0 + (px >> 3), gx = tx0 + (px & 7);
        qsm[idx] = qs[(gy * WDIM + gx) * HDim + c];
    }
    for (int i4 = t; i4 < NHALO * 8; i4 += 256) {
        int hp = i4 >> 3, c4 = (i4 & 7) * 4;
        int hy = hp / HC, hx = hp - hy * HC;
        int gy = ty0 - MAXDIS + hy, gx = tx0 - MAXDIS + hx;
        float4 vv = make_float4(0.f, 0.f, 0.f, 0.f);
        if ((unsigned)gy < 32u && (unsigned)gx < 32u)
            vv = *(const float4*)&kp[(gy * WDIM + gx) * HDim + c4];
        *(float4*)&ksm[hp * KSTR + c4] = vv;
    }
    __syncthreads();

    if (t < WS2) {
        const int s  = t;
        const int kh = s / WS;
        const int kw = s - kh * WS;
        float wreg[32];
#pragma unroll
        for (int c4 = 0; c4 < 32; c4 += 4) {
            float4 w4 = *(const float4*)&Wrk[(h * WS2 + s) * HDim + c4];
            wreg[c4]     = T_CONST * w4.x;
            wreg[c4 + 1] = T_CONST * w4.y;
            wreg[c4 + 2] = T_CONST * w4.z;
            wreg[c4 + 3] = T_CONST * w4.w;
        }
        const float bb = brk[h * WS2 + s];
        const int aoff = kh * 16 + kw;

#pragma unroll
        for (int py = 0; py < TH; py++) {
            const int gy = ty0 + py + kh - MAXDIS;
            const bool vy = ((unsigned)gy < 32u);
            const int hrow = (py + kh) * HC;
#pragma unroll
            for (int pxx = 0; pxx < TW; pxx++) {
                const int gx = tx0 + pxx + kw - MAXDIS;
                const float* kr = &ksm[(hrow + pxx + kw) * KSTR];
                const float* qr = &qsm[(py * TW + pxx) * 32];
                float a = bb;
#pragma unroll
                for (int c4 = 0; c4 < 32; c4 += 4) {
                    float4 qv = *(const float4*)(qr + c4);
                    float4 kv = *(const float4*)(kr + c4);
                    a += qv.x * kv.x + qv.y * kv.y + qv.z * kv.z + qv.w * kv.w;
                    a += qv.x * wreg[c4]     + qv.y * wreg[c4 + 1]
                       + qv.z * wreg[c4 + 2] + qv.w * wreg[c4 + 3];
                }
                if (!(vy && (unsigned)gx < 32u)) a -= 1e8f;
                atsm[(py * TW + pxx) * ASTR + aoff] = a;
            }
        }
    }
    __syncthreads();

    for (int i4 = t; i4 < NHALO * 8; i4 += 256) {
        int hp = i4 >> 3, c4 = (i4 & 7) * 4;
        int hy = hp / HC, hx = hp - hy * HC;
        int gy = ty0 - MAXDIS + hy, gx = tx0 - MAXDIS + hx;
        float4 vv = make_float4(0.f, 0.f, 0.f, 0.f);
        if ((unsigned)gy < 32u && (unsigned)gx < 32u)
            vv = *(const float4*)&vp[(gy * WDIM + gx) * HDim + c4];
        *(float4*)&ksm[hp * KSTR + c4] = vv;
    }

    {
        const int warp = t >> 5, lane = t & 31;
#pragma unroll
        for (int pp = 0; pp < 4; pp++) {
            const int px = warp * 4 + pp;
            float* arow = &atsm[px * ASTR];
            if (lane < 15) arow[lane * 16 + 15] = 0.f;
            float vals[8];
            int   offs[8];
            float mx = -3.4e38f;
#pragma unroll
            for (int i = 0; i < 8; i++) {
                int s = lane + 32 * i;
                if (s < WS2) {
                    offs[i] = (s / WS) * 16 + (s % WS);
                    vals[i] = arow[offs[i]];
                } else { offs[i] = -1; vals[i] = -3.4e38f; }
                mx = fmaxf(mx, vals[i]);
            }
#pragma unroll
            for (int off = 16; off; off >>= 1)
                mx = fmaxf(mx, __shfl_xor_sync(0xffffffffu, mx, off));
            float sum = 0.f;
#pragma unroll
            for (int i = 0; i < 8; i++) {
                float e = (offs[i] >= 0) ? __expf(vals[i] - mx) : 0.f;
                vals[i] = e;
                sum += e;
            }
#pragma unroll
            for (int off = 16; off; off >>= 1)
                sum += __shfl_xor_sync(0xffffffffu, sum, off);
            const float inv = 1.0f / sum;
#pragma unroll
            for (int i = 0; i < 8; i++)
                if (offs[i] >= 0) arow[offs[i]] = vals[i] * inv;
        }
    }
    __syncthreads();

    if (attn_out) {
        float* ao = attn_out + (size_t)nh * WS2 * HW;
        for (int idx = t; idx < WS2 * TPIX; idx += 256) {
            int px = idx & 31, s = idx >> 5;
            int off = (s / WS) * 16 + (s % WS);
            int pgl = (ty0 + (px >> 3)) * WDIM + tx0 + (px & 7);
            ao[s * HW + pgl] = atsm[px * ASTR + off];
        }
    }

    {
        const int c    = t & 31;
        const int warp = t >> 5;
        const int py   = warp & 3;
        const int half = warp >> 2;
        const int kh0  = half ? 8 : 0;
        const int kh1  = half ? 15 : 8;
        const float* rvh = g_rvT + (size_t)h * WS2 * HDim;

        float acc[TW];
#pragma unroll
        for (int i = 0; i < TW; i++) acc[i] = 0.f;

        for (int kh = kh0; kh < kh1; kh++) {
            const int hy = py + kh;
            float vreg[HC];
#pragma unroll
            for (int x = 0; x < HC; x++)
                vreg[x] = ksm[(hy * HC + x) * KSTR + c];
            float rreg[WS];
#pragma unroll
            for (int kw = 0; kw < WS; kw++)
                rreg[kw] = rvh[(kh * WS + kw) * HDim + c];

#pragma unroll
            for (int pxx = 0; pxx < TW; pxx++) {
                const float* arow = &atsm[(py * TW + pxx) * ASTR + kh * 16];
                float4 a0 = *(const float4*)(arow);
                float4 a1 = *(const float4*)(arow + 4);
                float4 a2 = *(const float4*)(arow + 8);
                float4 a3 = *(const float4*)(arow + 12);
                float av[15] = {a0.x, a0.y, a0.z, a0.w, a1.x, a1.y, a1.z, a1.w,
                                a2.x, a2.y, a2.z, a2.w, a3.x, a3.y, a3.z};
                float s0 = 0.f;
#pragma unroll
                for (int kw = 0; kw < WS; kw++) {
                    acc[pxx] += av[kw] * vreg[pxx + kw];
                    s0       += av[kw] * rreg[kw];
                }
                acc[pxx] += s0;
            }
        }

        if (half == 1) {
#pragma unroll
            for (int pxx = 0; pxx < TW; pxx++)
                qsm[(py * TW + pxx) * 32 + c] = acc[pxx];
        }
        __syncthreads();
        if (half == 0) {
#pragma unroll
            for (int pxx = 0; pxx < TW; pxx++) {
                const int gy = ty0 + py, gx = tx0 + pxx;
                float tot = acc[pxx] + qsm[(py * TW + pxx) * 32 + c];
                g_ao[((size_t)n * HW + gy * WDIM + gx) * CCH + h * HDim + c] = tot;
            }
        }
    }
}

// ---------------------------------------------------------------------------
extern "C" void kernel_launch(void* const* d_in, const int* in_sizes, int n_in,
                              void* d_out, int out_size)
{
    const float* q     = (const float*)d_in[0];
    const float* k     = (const float*)d_in[1];
    const float* v     = (const float*)d_in[2];
    const float* WQ    = (const float*)d_in[3];
    const float* bQ    = (const float*)d_in[4];
    const float* WK    = (const float*)d_in[5];
    const float* bK    = (const float*)d_in[6];
    const float* WV    = (const float*)d_in[7];
    const float* bV    = (const float*)d_in[8];
    const float* Wrk   = (const float*)d_in[9];
    const float* brk   = (const float*)d_in[10];
    const float* rel_v = (const float*)d_in[11];
    const float* Wp    = (const float*)d_in[12];
    const float* bp    = (const float*)d_in[13];

    float* out = (float*)d_out;
    float* attn_out = nullptr;
    if (out_size >= OUT_ELEMS + ATTN_ELEMS)
        attn_out = out + OUT_ELEMS;

    cudaFuncSetAttribute(attn_kernel,
                         cudaFuncAttributeMaxDynamicSharedMemorySize, SMEM_BYTES);

    prep_w<<<256, 256>>>(WQ, WK, WV, Wp);
    prep_qkv<<<dim3(256, 3), 256>>>(q, k, v);
    rvT_kernel<<<(HNUM * WS2 * HDim + 255) / 256, 256>>>(rel_v);
    proj_gemm<<<dim3(32, 8, 3), 128>>>(bQ, bK, bV);
    attn_kernel<<<dim3(32, HNUM, NB), 256, SMEM_BYTES>>>(Wrk, brk, attn_out);
    prep_ao<<<256, 256>>>();
    final_gemm<<<dim3(32, 8), 128>>>(bp, out);
}

// round 9
// speedup vs baseline: 1.9023x; 1.0784x over previous
#include <cuda_runtime.h>
#include <cuda_bf16.h>
#include <cstdint>

// ---------------------------------------------------------------------------
// MultiheadLocalAttentionV1: N=2, C=256, H=8, HD=32, 32x32 spatial,
// 15x15 window (225 taps), dilation 1, pad 7.
//
//   prep_all   : split weights + q/k/v into bf16 hi/lo fragments, rel_v^T
//   proj_gemm  : qp/kp/vp = X@W^T + b via bf16 mma (2-way split, fp32 acc)
//   attn_kernel: local attention (fp32 SIMT, ILP-restructured)
//   prep_ao    : split attention output into A-fragment layout
//   final_gemm : out = ao @ Wp^T + bp
// ---------------------------------------------------------------------------

#define NB      2
#define HNUM    8
#define HDim    32
#define CCH     256
#define WDIM    32
#define HW      1024
#define WS      15
#define WS2     225
#define MAXDIS  7

#define TW      8
#define TH      4
#define TPIX    32
#define HR      (TH + 14)   // 18
#define HC      (TW + 14)   // 22
#define NHALO   (HR * HC)   // 396
#define KSTR    36
#define ASTR    244

#define T_CONST 5.656854249492381f
#define INV_T   0.17677669529663689f

#define OUT_ELEMS  (HW * NB * CCH)
#define ATTN_ELEMS (NB * HNUM * WS2 * HW)

// attn smem layout (floats)
#define S_K 0
#define S_A (NHALO * KSTR)
#define S_Q (S_A + TPIX * ASTR)
#define SMEM_FLOATS (S_Q + TPIX * HDim)
#define SMEM_BYTES  (SMEM_FLOATS * 4)       // 92352 B

// fragment-array sizes
#define AFRAGS  65536   // per matrix: 128 m16 x 16 k16 x 32 lanes (uint4)
#define BFRAGS  16384   // per matrix: 32 n8 x 16 k16 x 32 lanes (uint2)

// -------------------------- global scratch ---------------------------------
__device__ float g_qs[NB * HNUM * HW * HDim];
__device__ float g_kp[NB * HNUM * HW * HDim];
__device__ float g_vp[NB * HNUM * HW * HDim];
__device__ float g_ao[NB * HW * CCH];
__device__ float g_rvT[HNUM * WS2 * HDim];

__device__ uint4 g_Ahi[4 * AFRAGS];   // slots: 0=q 1=k 2=v 3=ao
__device__ uint4 g_Alo[4 * AFRAGS];
__device__ uint2 g_Bhi[4 * BFRAGS];   // slots: 0=WQ 1=WK 2=WV 3=Wp
__device__ uint2 g_Blo[4 * BFRAGS];

// ---------------------------------------------------------------------------
// bf16 helpers
// ---------------------------------------------------------------------------
__device__ __forceinline__ uint32_t pack2(float even_k, float odd_k) {
    __nv_bfloat162 t = __floats2bfloat162_rn(even_k, odd_k);  // .x = low half
    return *reinterpret_cast<uint32_t*>(&t);
}
__device__ __forceinline__ void split1(float x, float& hi, float& lo) {
    hi = __bfloat162float(__float2bfloat16(x));
    lo = x - hi;
}
__device__ __forceinline__ void mma_bf16(float* acc, uint4 a, uint2 b) {
    asm volatile(
        "mma.sync.aligned.m16n8k16.row.col.f32.bf16.bf16.f32 "
        "{%0,%1,%2,%3},{%4,%5,%6,%7},{%8,%9},{%0,%1,%2,%3};\n"
        : "+f"(acc[0]), "+f"(acc[1]), "+f"(acc[2]), "+f"(acc[3])
        : "r"(a.x), "r"(a.y), "r"(a.z), "r"(a.w), "r"(b.x), "r"(b.y));
}

// ---------------------------------------------------------------------------
// prep_all: one kernel covering three independent prep jobs.
//   blocks [0, 256)      : weight split  (WQ/WK/WV/Wp -> B fragments)
//   blocks [256, 1024)   : q/k/v split   (-> A fragments, slots 0-2)
//   blocks [1024, 1249)  : rel_v transpose
// ---------------------------------------------------------------------------
__global__ __launch_bounds__(256) void prep_all(
    const float* __restrict__ q, const float* __restrict__ k,
    const float* __restrict__ v,
    const float* __restrict__ WQ, const float* __restrict__ WK,
    const float* __restrict__ WV, const float* __restrict__ Wp,
    const float* __restrict__ rel_v)
{
    const int b = blockIdx.x;

    if (b < 256) {
        // ---- weight split ----
        int tid  = b * 256 + threadIdx.x;
        int lane = tid & 31;
        int k16  = (tid >> 5) & 15;
        int n8   = (tid >> 9) & 31;
        int mat  = tid >> 14;
        const float* W = (mat == 0) ? WQ : (mat == 1) ? WK : (mat == 2) ? WV : Wp;

        int g = lane >> 2, tig = lane & 3;
        int n  = n8 * 8 + g;
        int kb = k16 * 16 + 2 * tig;

        const float* r = W + (size_t)n * 256;
        float h0, l0, h1, l1, h8, l8, h9, l9;
        split1(r[kb],     h0, l0);
        split1(r[kb + 1], h1, l1);
        split1(r[kb + 8], h8, l8);
        split1(r[kb + 9], h9, l9);

        size_t idx = ((size_t)(mat * 32 + n8) * 16 + k16) * 32 + lane;
        g_Bhi[idx] = make_uint2(pack2(h0, h1), pack2(h8, h9));
        g_Blo[idx] = make_uint2(pack2(l0, l1), pack2(l8, l9));
    } else if (b < 1024) {
        // ---- q/k/v activation split ----
        int mat = (b - 256) >> 8;
        const float* src = (mat == 0) ? q : (mat == 1) ? k : v;

        int tid  = ((b - 256) & 255) * 256 + threadIdx.x;   // 0..65535
        int lane = tid & 31;
        int k16  = (tid >> 5) & 15;
        int m16  = tid >> 9;
        int g = lane >> 2, tig = lane & 3;
        int r0 = m16 * 16 + g;
        int r1 = r0 + 8;
        int kb = k16 * 16 + 2 * tig;

        int n0 = r0 >> 10, p0 = r0 & 1023;
        int n1 = r1 >> 10, p1 = r1 & 1023;

        uint32_t hi[4], lo[4];
#pragma unroll
        for (int j = 0; j < 4; j++) {
            int row_n = (j & 1) ? n1 : n0;
            int row_p = (j & 1) ? p1 : p0;
            int kc = kb + ((j >> 1) ? 8 : 0);
            float f0 = src[((size_t)(row_n * 256 + kc)) * 1024 + row_p];
            float f1 = src[((size_t)(row_n * 256 + kc + 1)) * 1024 + row_p];
            float h0, l0, h1, l1;
            split1(f0, h0, l0);
            split1(f1, h1, l1);
            hi[j] = pack2(h0, h1);
            lo[j] = pack2(l0, l1);
        }
        size_t idx = (size_t)mat * AFRAGS + ((size_t)m16 * 16 + k16) * 32 + lane;
        g_Ahi[idx] = make_uint4(hi[0], hi[1], hi[2], hi[3]);
        g_Alo[idx] = make_uint4(lo[0], lo[1], lo[2], lo[3]);
    } else {
        // ---- rel_v transpose (H,HD,WS2) -> (H,WS2,HD) ----
        int i = (b - 1024) * 256 + threadIdx.x;
        if (i < HNUM * WS2 * HDim) {
            int c = i & 31;
            int s = (i >> 5) % WS2;
            int h = i / (WS2 * HDim);
            g_rvT[i] = rel_v[(h * HDim + c) * WS2 + s];
        }
    }
}

// ---------------------------------------------------------------------------
// prep_ao: split g_ao (row-major [2048][256]) into A-fragment slot 3.
// ---------------------------------------------------------------------------
__global__ __launch_bounds__(256) void prep_ao()
{
    int tid  = blockIdx.x * 256 + threadIdx.x;   // 65536
    int lane = tid & 31;
    int k16  = (tid >> 5) & 15;
    int m16  = tid >> 9;
    int g = lane >> 2, tig = lane & 3;
    int r0 = m16 * 16 + g;
    int kb = k16 * 16 + 2 * tig;

    uint32_t hi[4], lo[4];
#pragma unroll
    for (int j = 0; j < 4; j++) {
        int row = r0 + ((j & 1) ? 8 : 0);
        int kc  = kb + ((j >> 1) ? 8 : 0);
        float2 f = *(const float2*)&g_ao[(size_t)row * 256 + kc];
        float h0, l0, h1, l1;
        split1(f.x, h0, l0);
        split1(f.y, h1, l1);
        hi[j] = pack2(h0, h1);
        lo[j] = pack2(l0, l1);
    }
    size_t idx = (size_t)3 * AFRAGS + ((size_t)m16 * 16 + k16) * 32 + lane;
    g_Ahi[idx] = make_uint4(hi[0], hi[1], hi[2], hi[3]);
    g_Alo[idx] = make_uint4(lo[0], lo[1], lo[2], lo[3]);
}

// ---------------------------------------------------------------------------
// GEMM core: warp computes 16m x 16n over K=256. No smem.
// ---------------------------------------------------------------------------
__device__ __forceinline__ void gemm_core(
    const uint4* __restrict__ Ahi, const uint4* __restrict__ Alo,
    const uint2* __restrict__ Bhi, const uint2* __restrict__ Blo,
    int m16, int n8b, int lane, float acc[2][4])
{
#pragma unroll 4
    for (int k16 = 0; k16 < 16; k16++) {
        uint4 ah = Ahi[((size_t)m16 * 16 + k16) * 32 + lane];
        uint4 al = Alo[((size_t)m16 * 16 + k16) * 32 + lane];
#pragma unroll
        for (int nt = 0; nt < 2; nt++) {
            size_t bi = ((size_t)(n8b + nt) * 16 + k16) * 32 + lane;
            uint2 bh = Bhi[bi];
            uint2 bl = Blo[bi];
            mma_bf16(acc[nt], ah, bh);
            mma_bf16(acc[nt], ah, bl);
            mma_bf16(acc[nt], al, bh);
        }
    }
}

// ---------------------------------------------------------------------------
// proj_gemm: grid (32 m-blocks, 16 n-blocks, 3 mats), 128 threads (4 warps).
// Writes (n,h,p,hd); q scaled by 1/T.
// ---------------------------------------------------------------------------
__global__ __launch_bounds__(128) void proj_gemm(
    const float* __restrict__ bQ, const float* __restrict__ bK,
    const float* __restrict__ bV)
{
    const int mat  = blockIdx.z;
    const int warp = threadIdx.x >> 5;
    const int lane = threadIdx.x & 31;
    const int m16  = blockIdx.x * 4 + warp;
    const int n8b  = blockIdx.y * 2;

    const uint4* Ahi = g_Ahi + (size_t)mat * AFRAGS;
    const uint4* Alo = g_Alo + (size_t)mat * AFRAGS;
    const uint2* Bhi = g_Bhi + (size_t)mat * BFRAGS;
    const uint2* Blo = g_Blo + (size_t)mat * BFRAGS;

    float acc[2][4];
#pragma unroll
    for (int i = 0; i < 2; i++)
#pragma unroll
        for (int j = 0; j < 4; j++) acc[i][j] = 0.f;

    gemm_core(Ahi, Alo, Bhi, Blo, m16, n8b, lane, acc);

    const float* b = (mat == 0) ? bQ : (mat == 1) ? bK : bV;
    float* out     = (mat == 0) ? g_qs : (mat == 1) ? g_kp : g_vp;
    const float scale = (mat == 0) ? INV_T : 1.0f;

    const int g = lane >> 2, tig = lane & 3;
    const int r0 = m16 * 16 + g;
#pragma unroll
    for (int nt = 0; nt < 2; nt++) {
        const int o0 = (n8b + nt) * 8 + 2 * tig;
        const int h = o0 >> 5, hd = o0 & 31;
        const float b0 = b[o0], b1 = b[o0 + 1];
#pragma unroll
        for (int rr = 0; rr < 2; rr++) {
            const int r = r0 + rr * 8;
            const int n_b = r >> 10, p = r & 1023;
            float2 val;
            val.x = (acc[nt][rr * 2]     + b0) * scale;
            val.y = (acc[nt][rr * 2 + 1] + b1) * scale;
            *(float2*)&out[((size_t)(n_b * HNUM + h) * HW + p) * HDim + hd] = val;
        }
    }
}

// ---------------------------------------------------------------------------
// final_gemm: grid (32, 16), 128 threads. out[(p*NB+n)*256+o] = ao@Wp^T + bp
// ---------------------------------------------------------------------------
__global__ __launch_bounds__(128) void final_gemm(
    const float* __restrict__ bp, float* __restrict__ out)
{
    const int warp = threadIdx.x >> 5;
    const int lane = threadIdx.x & 31;
    const int m16  = blockIdx.x * 4 + warp;
    const int n8b  = blockIdx.y * 2;

    const uint4* Ahi = g_Ahi + (size_t)3 * AFRAGS;
    const uint4* Alo = g_Alo + (size_t)3 * AFRAGS;
    const uint2* Bhi = g_Bhi + (size_t)3 * BFRAGS;
    const uint2* Blo = g_Blo + (size_t)3 * BFRAGS;

    float acc[2][4];
#pragma unroll
    for (int i = 0; i < 2; i++)
#pragma unroll
        for (int j = 0; j < 4; j++) acc[i][j] = 0.f;

    gemm_core(Ahi, Alo, Bhi, Blo, m16, n8b, lane, acc);

    const int g = lane >> 2, tig = lane & 3;
    const int r0 = m16 * 16 + g;
#pragma unroll
    for (int nt = 0; nt < 2; nt++) {
        const int o0 = (n8b + nt) * 8 + 2 * tig;
        const float b0 = bp[o0], b1 = bp[o0 + 1];
#pragma unroll
        for (int rr = 0; rr < 2; rr++) {
            const int r = r0 + rr * 8;
            const int n_b = r >> 10, p = r & 1023;
            float2 val;
            val.x = acc[nt][rr * 2]     + b0;
            val.y = acc[nt][rr * 2 + 1] + b1;
            *(float2*)&out[((size_t)p * NB + n_b) * CCH + o0] = val;
        }
    }
}

// ---------------------------------------------------------------------------
// attn_kernel: local attention. grid = (32 tiles, 8 heads, 2 batch), 256 thr.
// ---------------------------------------------------------------------------
extern __shared__ float sm[];

__global__ __launch_bounds__(256) void attn_kernel(
    const float* __restrict__ Wrk, const float* __restrict__ brk,
    float* __restrict__ attn_out)
{
    const int h = blockIdx.y;
    const int n = blockIdx.z;
    const int tileIdx = blockIdx.x;
    const int tx0 = (tileIdx & 3) * TW;
    const int ty0 = (tileIdx >> 2) * TH;
    const int t = threadIdx.x;
    const int nh = n * HNUM + h;

    const float* qs = g_qs + (size_t)nh * HW * HDim;
    const float* kp = g_kp + (size_t)nh * HW * HDim;
    const float* vp = g_vp + (size_t)nh * HW * HDim;

    float* ksm  = sm + S_K;
    float* atsm = sm + S_A;
    float* qsm  = sm + S_Q;

    for (int idx = t; idx < TPIX * 32; idx += 256) {
        int px = idx >> 5, c = idx & 31;
        int gy = ty0 + (px >> 3), gx = tx0 + (px & 7);
        qsm[idx] = qs[(gy * WDIM + gx) * HDim + c];
    }
    for (int i4 = t; i4 < NHALO * 8; i4 += 256) {
        int hp = i4 >> 3, c4 = (i4 & 7) * 4;
        int hy = hp / HC, hx = hp - hy * HC;
        int gy = ty0 - MAXDIS + hy, gx = tx0 - MAXDIS + hx;
        float4 vv = make_float4(0.f, 0.f, 0.f, 0.f);
        if ((unsigned)gy < 32u && (unsigned)gx < 32u)
            vv = *(const float4*)&kp[(gy * WDIM + gx) * HDim + c4];
        *(float4*)&ksm[hp * KSTR + c4] = vv;
    }
    __syncthreads();

    // ---- logits: thread = tap s, 2 pixels per iteration, 4 FMA chains ----
    if (t < WS2) {
        const int s  = t;
        const int kh = s / WS;
        const int kw = s - kh * WS;
        float wreg[32];
#pragma unroll
        for (int c4 = 0; c4 < 32; c4 += 4) {
            float4 w4 = *(const float4*)&Wrk[(h * WS2 + s) * HDim + c4];
            wreg[c4]     = T_CONST * w4.x;
            wreg[c4 + 1] = T_CONST * w4.y;
            wreg[c4 + 2] = T_CONST * w4.z;
            wreg[c4 + 3] = T_CONST * w4.w;
        }
        const float bb = brk[h * WS2 + s];
        const int aoff = kh * 16 + kw;

#pragma unroll
        for (int py = 0; py < TH; py++) {
            const int gy = ty0 + py + kh - MAXDIS;
            const bool vy = ((unsigned)gy < 32u);
            const int hrow = (py + kh) * HC;
#pragma unroll
            for (int pp = 0; pp < TW; pp += 2) {
                const float* kr0 = &ksm[(hrow + pp + kw) * KSTR];
                const float* kr1 = kr0 + KSTR;
                const float* qr0 = &qsm[(py * TW + pp) * 32];
                const float* qr1 = qr0 + 32;
                float aK0 = 0.f, aW0 = 0.f, aK1 = 0.f, aW1 = 0.f;
#pragma unroll
                for (int c4 = 0; c4 < 32; c4 += 4) {
                    float4 q0 = *(const float4*)(qr0 + c4);
                    float4 q1 = *(const float4*)(qr1 + c4);
                    float4 k0 = *(const float4*)(kr0 + c4);
                    float4 k1 = *(const float4*)(kr1 + c4);
                    aK0 += q0.x * k0.x + q0.y * k0.y + q0.z * k0.z + q0.w * k0.w;
                    aK1 += q1.x * k1.x + q1.y * k1.y + q1.z * k1.z + q1.w * k1.w;
                    aW0 += q0.x * wreg[c4]     + q0.y * wreg[c4 + 1]
                         + q0.z * wreg[c4 + 2] + q0.w * wreg[c4 + 3];
                    aW1 += q1.x * wreg[c4]     + q1.y * wreg[c4 + 1]
                         + q1.z * wreg[c4 + 2] + q1.w * wreg[c4 + 3];
                }
                float a0 = bb + aK0 + aW0;
                float a1 = bb + aK1 + aW1;
                const int gx0 = tx0 + pp + kw - MAXDIS;
                if (!(vy && (unsigned)gx0 < 32u))       a0 -= 1e8f;
                if (!(vy && (unsigned)(gx0 + 1) < 32u)) a1 -= 1e8f;
                atsm[(py * TW + pp) * ASTR + aoff]     = a0;
                atsm[(py * TW + pp + 1) * ASTR + aoff] = a1;
            }
        }
    }
    __syncthreads();

    // ---- overwrite halo with V (overlaps softmax latency) ----
    for (int i4 = t; i4 < NHALO * 8; i4 += 256) {
        int hp = i4 >> 3, c4 = (i4 & 7) * 4;
        int hy = hp / HC, hx = hp - hy * HC;
        int gy = ty0 - MAXDIS + hy, gx = tx0 - MAXDIS + hx;
        float4 vv = make_float4(0.f, 0.f, 0.f, 0.f);
        if ((unsigned)gy < 32u && (unsigned)gx < 32u)
            vv = *(const float4*)&vp[(gy * WDIM + gx) * HDim + c4];
        *(float4*)&ksm[hp * KSTR + c4] = vv;
    }

    // ---- softmax: warp handles 4 pixels ----
    {
        const int warp = t >> 5, lane = t & 31;
#pragma unroll
        for (int pp = 0; pp < 4; pp++) {
            const int px = warp * 4 + pp;
            float* arow = &atsm[px * ASTR];
            if (lane < 15) arow[lane * 16 + 15] = 0.f;
            float vals[8];
            int   offs[8];
            float mx = -3.4e38f;
#pragma unroll
            for (int i = 0; i < 8; i++) {
                int s = lane + 32 * i;
                if (s < WS2) {
                    offs[i] = (s / WS) * 16 + (s % WS);
                    vals[i] = arow[offs[i]];
                } else { offs[i] = -1; vals[i] = -3.4e38f; }
                mx = fmaxf(mx, vals[i]);
            }
#pragma unroll
            for (int off = 16; off; off >>= 1)
                mx = fmaxf(mx, __shfl_xor_sync(0xffffffffu, mx, off));
            float sum = 0.f;
#pragma unroll
            for (int i = 0; i < 8; i++) {
                float e = (offs[i] >= 0) ? __expf(vals[i] - mx) : 0.f;
                vals[i] = e;
                sum += e;
            }
#pragma unroll
            for (int off = 16; off; off >>= 1)
                sum += __shfl_xor_sync(0xffffffffu, sum, off);
            const float inv = 1.0f / sum;
#pragma unroll
            for (int i = 0; i < 8; i++)
                if (offs[i] >= 0) arow[offs[i]] = vals[i] * inv;
        }
    }
    __syncthreads();

    // ---- write attn probabilities (n,H,WS2,hw) ----
    if (attn_out) {
        float* ao = attn_out + (size_t)nh * WS2 * HW;
        for (int idx = t; idx < WS2 * TPIX; idx += 256) {
            int px = idx & 31, s = idx >> 5;
            int off = (s / WS) * 16 + (s % WS);
            int pgl = (ty0 + (px >> 3)) * WDIM + tx0 + (px & 7);
            ao[s * HW + pgl] = atsm[px * ASTR + off];
        }
    }

    // ---- output: sliding-window register scheme ----
    {
        const int c    = t & 31;
        const int warp = t >> 5;
        const int py   = warp & 3;
        const int half = warp >> 2;
        const int kh0  = half ? 8 : 0;
        const int kh1  = half ? 15 : 8;
        const float* rvh = g_rvT + (size_t)h * WS2 * HDim;

        float acc[TW];
#pragma unroll
        for (int i = 0; i < TW; i++) acc[i] = 0.f;

        for (int kh = kh0; kh < kh1; kh++) {
            const int hy = py + kh;
            float vreg[HC];
#pragma unroll
            for (int x = 0; x < HC; x++)
                vreg[x] = ksm[(hy * HC + x) * KSTR + c];
            float rreg[WS];
#pragma unroll
            for (int kw = 0; kw < WS; kw++)
                rreg[kw] = rvh[(kh * WS + kw) * HDim + c];

#pragma unroll
            for (int pxx = 0; pxx < TW; pxx++) {
                const float* arow = &atsm[(py * TW + pxx) * ASTR + kh * 16];
                float4 a0 = *(const float4*)(arow);
                float4 a1 = *(const float4*)(arow + 4);
                float4 a2 = *(const float4*)(arow + 8);
                float4 a3 = *(const float4*)(arow + 12);
                float av[15] = {a0.x, a0.y, a0.z, a0.w, a1.x, a1.y, a1.z, a1.w,
                                a2.x, a2.y, a2.z, a2.w, a3.x, a3.y, a3.z};
                float s0 = 0.f;
#pragma unroll
                for (int kw = 0; kw < WS; kw++) {
                    acc[pxx] += av[kw] * vreg[pxx + kw];
                    s0       += av[kw] * rreg[kw];
                }
                acc[pxx] += s0;
            }
        }

        if (half == 1) {
#pragma unroll
            for (int pxx = 0; pxx < TW; pxx++)
                qsm[(py * TW + pxx) * 32 + c] = acc[pxx];
        }
        __syncthreads();
        if (half == 0) {
#pragma unroll
            for (int pxx = 0; pxx < TW; pxx++) {
                const int gy = ty0 + py, gx = tx0 + pxx;
                float tot = acc[pxx] + qsm[(py * TW + pxx) * 32 + c];
                g_ao[((size_t)n * HW + gy * WDIM + gx) * CCH + h * HDim + c] = tot;
            }
        }
    }
}

// ---------------------------------------------------------------------------
extern "C" void kernel_launch(void* const* d_in, const int* in_sizes, int n_in,
                              void* d_out, int out_size)
{
    const float* q     = (const float*)d_in[0];
    const float* k     = (const float*)d_in[1];
    const float* v     = (const float*)d_in[2];
    const float* WQ    = (const float*)d_in[3];
    const float* bQ    = (const float*)d_in[4];
    const float* WK    = (const float*)d_in[5];
    const float* bK    = (const float*)d_in[6];
    const float* WV    = (const float*)d_in[7];
    const float* bV    = (const float*)d_in[8];
    const float* Wrk   = (const float*)d_in[9];
    const float* brk   = (const float*)d_in[10];
    const float* rel_v = (const float*)d_in[11];
    const float* Wp    = (const float*)d_in[12];
    const float* bp    = (const float*)d_in[13];

    float* out = (float*)d_out;
    float* attn_out = nullptr;
    if (out_size >= OUT_ELEMS + ATTN_ELEMS)
        attn_out = out + OUT_ELEMS;

    cudaFuncSetAttribute(attn_kernel,
                         cudaFuncAttributeMaxDynamicSharedMemorySize, SMEM_BYTES);

    prep_all<<<1249, 256>>>(q, k, v, WQ, WK, WV, Wp, rel_v);
    proj_gemm<<<dim3(32, 16, 3), 128>>>(bQ, bK, bV);
    attn_kernel<<<dim3(32, HNUM, NB), 256, SMEM_BYTES>>>(Wrk, brk, attn_out);
    prep_ao<<<256, 256>>>();
    final_gemm<<<dim3(32, 16), 128>>>(bp, out);
}